// round 1
// baseline (speedup 1.0000x reference)
#include <cuda_runtime.h>
#include <math.h>

#define B2   32
#define T    512
#define DD   512
#define H    8
#define DH   64
#define TE   2048
#define NTOK (B2*T)          /* 16384 */
#define NELEM ((size_t)NTOK*DD) /* 8388608 */

// ---------------- scratch (static device memory; no allocation) ----------------
#define OFF_XN ((size_t)0)
#define OFF_TN (OFF_XN + NELEM)
#define OFF_Q  (OFF_TN + NELEM)   // head layout [b,h,n,dh]
#define OFF_K  (OFF_Q  + NELEM)
#define OFF_V  (OFF_K  + NELEM)
#define OFF_Y  (OFF_V  + NELEM)   // [b,n,D]
#define OFF_HS (OFF_Y  + NELEM)
#define OFF_S  (OFF_HS + NELEM)   // scores [bh, n, m]
#define OFF_SS (OFF_S  + (size_t)B2*H*T*T)
#define SCRATCH_TOTAL (OFF_SS + (size_t)B2*2*DD)

__device__ float g_scratch[SCRATCH_TOTAL];

// ---------------- LayerNorm for xn (from xa) and tn (from xb) ----------------
// xa[b] = b<16 ? x1[b] : x2[b-16];  xb[b] = b<16 ? x2[b] : x1[b-16]
__global__ void ln_kernel(const float* __restrict__ x1, const float* __restrict__ x2,
                          const float* __restrict__ gx, const float* __restrict__ bx,
                          const float* __restrict__ gt, const float* __restrict__ bt) {
    int rid = blockIdx.x;              // 0 .. 2*NTOK-1
    bool is_t = rid >= NTOK;
    int r = is_t ? rid - NTOK : rid;
    const float* src;
    if (!is_t) src = (r < NTOK/2) ? x1 + (size_t)r*DD : x2 + (size_t)(r - NTOK/2)*DD;
    else       src = (r < NTOK/2) ? x2 + (size_t)r*DD : x1 + (size_t)(r - NTOK/2)*DD;
    float* dst = g_scratch + (is_t ? OFF_TN : OFF_XN) + (size_t)r*DD;
    const float* g  = is_t ? gt : gx;
    const float* be = is_t ? bt : bx;

    int tid = threadIdx.x;             // 128 threads, 4 floats each
    float4 v = ((const float4*)src)[tid];
    float s  = v.x + v.y + v.z + v.w;
    float sq = v.x*v.x + v.y*v.y + v.z*v.z + v.w*v.w;

    __shared__ float red[2][4];
    #pragma unroll
    for (int o = 16; o; o >>= 1) {
        s  += __shfl_xor_sync(0xffffffffu, s,  o);
        sq += __shfl_xor_sync(0xffffffffu, sq, o);
    }
    int w = tid >> 5;
    if ((tid & 31) == 0) { red[0][w] = s; red[1][w] = sq; }
    __syncthreads();
    s  = red[0][0] + red[0][1] + red[0][2] + red[0][3];
    sq = red[1][0] + red[1][1] + red[1][2] + red[1][3];
    float mean = s * (1.0f/DD);
    float var  = sq * (1.0f/DD) - mean*mean;
    float inv  = rsqrtf(var + 1e-5f);

    float4 gg = ((const float4*)g)[tid];
    float4 bb = ((const float4*)be)[tid];
    float4 o;
    o.x = (v.x-mean)*inv*gg.x + bb.x;
    o.y = (v.y-mean)*inv*gg.y + bb.y;
    o.z = (v.z-mean)*inv*gg.z + bb.z;
    o.w = (v.w-mean)*inv*gg.w + bb.w;
    ((float4*)dst)[tid] = o;
}

// ---------------- generic tiled SGEMM: C = A @ W + bias (+variants) ----------------
// M = NTOK, N = D, K = D. 64x64 tile, BK=16, 256 threads, 4x4 microtile.
// SEL 0: A=xn -> Q (head layout); 1: A=tn -> K; 2: A=tn -> V; 3: A=hs -> out (+residual xa)
template<int SEL>
__global__ void sgemm_kernel(const float* __restrict__ W, const float* __restrict__ bias,
                             const float* __restrict__ x1, const float* __restrict__ x2,
                             float* __restrict__ outp) {
    const float* A;
    float* C;
    if      (SEL == 0) { A = g_scratch + OFF_XN; C = g_scratch + OFF_Q; }
    else if (SEL == 1) { A = g_scratch + OFF_TN; C = g_scratch + OFF_K; }
    else if (SEL == 2) { A = g_scratch + OFF_TN; C = g_scratch + OFF_V; }
    else               { A = g_scratch + OFF_HS; C = outp; }

    const int BM = 64, BN = 64, BK = 16;
    __shared__ float As[BK][BM + 1];
    __shared__ float Bs[BK][BN];

    int tid = threadIdx.x;
    int tx = tid & 15, ty = tid >> 4;
    int m0 = blockIdx.y * BM, n0 = blockIdx.x * BN;

    int lmA = tid >> 2;            // 0..63
    int lkA = (tid & 3) * 4;       // 0..12
    int lkB = tid >> 4;            // 0..15
    int lnB = (tid & 15) * 4;      // 0..60

    float acc[4][4] = {};

    for (int k0 = 0; k0 < DD; k0 += BK) {
        float4 av = *(const float4*)(A + (size_t)(m0 + lmA)*DD + k0 + lkA);
        As[lkA+0][lmA] = av.x; As[lkA+1][lmA] = av.y;
        As[lkA+2][lmA] = av.z; As[lkA+3][lmA] = av.w;
        float4 bv = *(const float4*)(W + (size_t)(k0 + lkB)*DD + n0 + lnB);
        *(float4*)&Bs[lkB][lnB] = bv;
        __syncthreads();
        #pragma unroll
        for (int kk = 0; kk < BK; kk++) {
            float a[4], b[4];
            #pragma unroll
            for (int i = 0; i < 4; i++) a[i] = As[kk][ty*4 + i];
            #pragma unroll
            for (int j = 0; j < 4; j++) b[j] = Bs[kk][tx*4 + j];
            #pragma unroll
            for (int i = 0; i < 4; i++)
                #pragma unroll
                for (int j = 0; j < 4; j++)
                    acc[i][j] += a[i] * b[j];
        }
        __syncthreads();
    }

    #pragma unroll
    for (int i = 0; i < 4; i++) {
        int m = m0 + ty*4 + i;
        #pragma unroll
        for (int j = 0; j < 4; j++) {
            int n = n0 + tx*4 + j;
            float v = acc[i][j] + bias[n];
            if (SEL < 3) {
                int b = m >> 9, nn = m & 511, h = n >> 6, d = n & 63;
                C[(((size_t)(b*H + h)*T + nn)*DH) + d] = v;
            } else {
                const float* src = (m < NTOK/2) ? x1 + (size_t)m*DD
                                                : x2 + (size_t)(m - NTOK/2)*DD;
                C[(size_t)m*DD + n] = v + src[n];
            }
        }
    }
}

// ---------------- attention scores: S[bh,n,m] = Q_h[n,:]·K_h[m,:] * 1/8 + mask ----------------
__global__ void scores_kernel(const float* __restrict__ mask) {
    __shared__ float Qs[64][65];
    __shared__ float Ks[64][65];
    int bh = blockIdx.z;
    int b  = bh >> 3;
    const float* Q = g_scratch + OFF_Q + (size_t)bh*T*DH;
    const float* K = g_scratch + OFF_K + (size_t)bh*T*DH;
    int n0 = blockIdx.y * 64, m0 = blockIdx.x * 64;
    int tid = threadIdx.x;

    int lr = tid >> 4;           // 0..15
    int lc = (tid & 15) * 4;     // 0..60
    #pragma unroll
    for (int p = 0; p < 4; p++) {
        int r = lr + p*16;
        float4 qv = *(const float4*)(Q + (size_t)(n0 + r)*DH + lc);
        Qs[r][lc+0]=qv.x; Qs[r][lc+1]=qv.y; Qs[r][lc+2]=qv.z; Qs[r][lc+3]=qv.w;
        float4 kv = *(const float4*)(K + (size_t)(m0 + r)*DH + lc);
        Ks[r][lc+0]=kv.x; Ks[r][lc+1]=kv.y; Ks[r][lc+2]=kv.z; Ks[r][lc+3]=kv.w;
    }
    __syncthreads();

    int tx = tid & 15, ty = tid >> 4;
    float acc[4][4] = {};
    #pragma unroll
    for (int d = 0; d < 64; d++) {
        float a[4], bv[4];
        #pragma unroll
        for (int i = 0; i < 4; i++) a[i]  = Qs[ty*4 + i][d];
        #pragma unroll
        for (int j = 0; j < 4; j++) bv[j] = Ks[tx*4 + j][d];
        #pragma unroll
        for (int i = 0; i < 4; i++)
            #pragma unroll
            for (int j = 0; j < 4; j++)
                acc[i][j] += a[i] * bv[j];
    }

    float* S = g_scratch + OFF_S + (size_t)bh*T*T;
    #pragma unroll
    for (int i = 0; i < 4; i++) {
        int n = n0 + ty*4 + i;
        #pragma unroll
        for (int j = 0; j < 4; j++) {
            int m = m0 + tx*4 + j;
            float mv = mask[((size_t)b*T + n)*T + m];
            S[(size_t)n*T + m] = acc[i][j]*0.125f + (1.0f - mv)*(-100000.0f);
        }
    }
}

// ---------------- row softmax over the key axis ----------------
__global__ void softmax_kernel() {
    float* row = g_scratch + OFF_S + (size_t)blockIdx.x * T;
    int tid = threadIdx.x;   // 128 threads, 4 vals each
    float4 v = ((const float4*)row)[tid];

    __shared__ float red[4];
    float mx = fmaxf(fmaxf(v.x, v.y), fmaxf(v.z, v.w));
    #pragma unroll
    for (int o = 16; o; o >>= 1) mx = fmaxf(mx, __shfl_xor_sync(0xffffffffu, mx, o));
    if ((tid & 31) == 0) red[tid >> 5] = mx;
    __syncthreads();
    mx = fmaxf(fmaxf(red[0], red[1]), fmaxf(red[2], red[3]));
    __syncthreads();

    float4 e;
    e.x = expf(v.x - mx); e.y = expf(v.y - mx);
    e.z = expf(v.z - mx); e.w = expf(v.w - mx);
    float s = e.x + e.y + e.z + e.w;
    #pragma unroll
    for (int o = 16; o; o >>= 1) s += __shfl_xor_sync(0xffffffffu, s, o);
    if ((tid & 31) == 0) red[tid >> 5] = s;
    __syncthreads();
    s = red[0] + red[1] + red[2] + red[3];
    float inv = 1.0f / s;
    e.x *= inv; e.y *= inv; e.z *= inv; e.w *= inv;
    ((float4*)row)[tid] = e;
}

// ---------------- Y_h[n,d] = S_h[n,:] @ V_h[:,d] ; written into [b,n,D] ----------------
__global__ void av_kernel() {
    const int BM = 64, BN = 64, BK = 16;
    __shared__ float Ss[BK][BM + 1];
    __shared__ float Vs[BK][BN];
    int bh = blockIdx.y;
    int b = bh >> 3, h = bh & 7;
    const float* S = g_scratch + OFF_S + (size_t)bh*T*T;
    const float* V = g_scratch + OFF_V + (size_t)bh*T*DH;
    int m0 = blockIdx.x * BM;
    int tid = threadIdx.x;
    int tx = tid & 15, ty = tid >> 4;

    int lmA = tid >> 2;
    int lkA = (tid & 3) * 4;
    int lkB = tid >> 4;
    int lnB = (tid & 15) * 4;

    float acc[4][4] = {};
    for (int k0 = 0; k0 < T; k0 += BK) {
        float4 av = *(const float4*)(S + (size_t)(m0 + lmA)*T + k0 + lkA);
        Ss[lkA+0][lmA]=av.x; Ss[lkA+1][lmA]=av.y; Ss[lkA+2][lmA]=av.z; Ss[lkA+3][lmA]=av.w;
        float4 bv = *(const float4*)(V + (size_t)(k0 + lkB)*DH + lnB);
        *(float4*)&Vs[lkB][lnB] = bv;
        __syncthreads();
        #pragma unroll
        for (int kk = 0; kk < BK; kk++) {
            float a[4], bb[4];
            #pragma unroll
            for (int i = 0; i < 4; i++) a[i]  = Ss[kk][ty*4 + i];
            #pragma unroll
            for (int j = 0; j < 4; j++) bb[j] = Vs[kk][tx*4 + j];
            #pragma unroll
            for (int i = 0; i < 4; i++)
                #pragma unroll
                for (int j = 0; j < 4; j++)
                    acc[i][j] += a[i] * bb[j];
        }
        __syncthreads();
    }
    float* Y = g_scratch + OFF_Y;
    #pragma unroll
    for (int i = 0; i < 4; i++) {
        int n = m0 + ty*4 + i;
        #pragma unroll
        for (int j = 0; j < 4; j++) {
            int d = tx*4 + j;
            Y[((size_t)b*T + n)*DD + h*DH + d] = acc[i][j];
        }
    }
}

// ---------------- emb FiLM params: g_ss[b, 0:512]=scale, [b,512:1024]=shift ----------------
__global__ void emb_kernel(const float* __restrict__ emb, const float* __restrict__ Wemb,
                           const float* __restrict__ bemb) {
    int b   = blockIdx.x >> 2;
    int col = (blockIdx.x & 3) * 256 + threadIdx.x;   // 0..1023
    __shared__ float se[256];
    float acc = 0.0f;
    for (int kc = 0; kc < TE; kc += 256) {
        float e = emb[(size_t)b*TE + kc + threadIdx.x];
        se[threadIdx.x] = e / (1.0f + expf(-e));
        __syncthreads();
        #pragma unroll 8
        for (int kk = 0; kk < 256; kk++)
            acc += se[kk] * Wemb[(size_t)(kc + kk)*(2*DD) + col];
        __syncthreads();
    }
    g_scratch[OFF_SS + (size_t)b*(2*DD) + col] = acc + bemb[col];
}

// ---------------- hs = silu( LN(y)*(1+scale) + shift ) ----------------
__global__ void film_kernel(const float* __restrict__ sbg, const float* __restrict__ sbb) {
    int r = blockIdx.x;                // 0..NTOK-1
    int b = r >> 9;
    const float* y = g_scratch + OFF_Y + (size_t)r*DD;
    float* dst = g_scratch + OFF_HS + (size_t)r*DD;
    const float* ss = g_scratch + OFF_SS + (size_t)b*(2*DD);

    int tid = threadIdx.x;             // 128
    float4 v = ((const float4*)y)[tid];
    float s  = v.x + v.y + v.z + v.w;
    float sq = v.x*v.x + v.y*v.y + v.z*v.z + v.w*v.w;
    __shared__ float red[2][4];
    #pragma unroll
    for (int o = 16; o; o >>= 1) {
        s  += __shfl_xor_sync(0xffffffffu, s,  o);
        sq += __shfl_xor_sync(0xffffffffu, sq, o);
    }
    if ((tid & 31) == 0) { red[0][tid>>5] = s; red[1][tid>>5] = sq; }
    __syncthreads();
    s  = red[0][0] + red[0][1] + red[0][2] + red[0][3];
    sq = red[1][0] + red[1][1] + red[1][2] + red[1][3];
    float mean = s * (1.0f/DD);
    float var  = sq * (1.0f/DD) - mean*mean;
    float inv  = rsqrtf(var + 1e-5f);

    int col = tid * 4;
    float vv[4] = {v.x, v.y, v.z, v.w};
    float4 o;
    float* op = &o.x;
    #pragma unroll
    for (int c = 0; c < 4; c++) {
        float ln = (vv[c] - mean) * inv * sbg[col + c] + sbb[col + c];
        float hh = ln * (1.0f + ss[col + c]) + ss[512 + col + c];
        op[c] = hh / (1.0f + expf(-hh));
    }
    ((float4*)dst)[tid] = o;
}

// ---------------- launch ----------------
extern "C" void kernel_launch(void* const* d_in, const int* in_sizes, int n_in,
                              void* d_out, int out_size) {
    const float* x1    = (const float*)d_in[0];
    const float* x2    = (const float*)d_in[1];
    const float* emb   = (const float*)d_in[2];
    const float* mask  = (const float*)d_in[3];
    const float* ln_x_g = (const float*)d_in[4];
    const float* ln_x_b = (const float*)d_in[5];
    const float* ln_t_g = (const float*)d_in[6];
    const float* ln_t_b = (const float*)d_in[7];
    const float* Wq = (const float*)d_in[8];
    const float* bq = (const float*)d_in[9];
    const float* Wk = (const float*)d_in[10];
    const float* bk = (const float*)d_in[11];
    const float* Wv = (const float*)d_in[12];
    const float* bv = (const float*)d_in[13];
    const float* Wemb = (const float*)d_in[14];
    const float* bemb = (const float*)d_in[15];
    const float* sb_g = (const float*)d_in[16];
    const float* sb_b = (const float*)d_in[17];
    const float* Wout = (const float*)d_in[18];
    const float* bout = (const float*)d_in[19];
    float* out = (float*)d_out;

    // LayerNorms for both streams
    ln_kernel<<<2*NTOK, 128>>>(x1, x2, ln_x_g, ln_x_b, ln_t_g, ln_t_b);

    // QKV projections (write per-head layout)
    dim3 gg(DD/64, NTOK/64);
    sgemm_kernel<0><<<gg, 256>>>(Wq, bq, x1, x2, nullptr);
    sgemm_kernel<1><<<gg, 256>>>(Wk, bk, x1, x2, nullptr);
    sgemm_kernel<2><<<gg, 256>>>(Wv, bv, x1, x2, nullptr);

    // emb FiLM params (independent; runs on same stream)
    emb_kernel<<<B2*4, 256>>>(emb, Wemb, bemb);

    // attention
    scores_kernel<<<dim3(T/64, T/64, B2*H), 256>>>(mask);
    softmax_kernel<<<B2*H*T, 128>>>();
    av_kernel<<<dim3(T/64, B2*H), 256>>>();

    // stylization + output projection + residual
    film_kernel<<<NTOK, 128>>>(sb_g, sb_b);
    sgemm_kernel<3><<<gg, 256>>>(Wout, bout, x1, x2, out);
}

// round 3
// speedup vs baseline: 2.0850x; 2.0850x over previous
#include <cuda_runtime.h>
#include <math.h>
#include <stdint.h>

#define B2   32
#define T    512
#define DD   512
#define H    8
#define DH   64
#define TE   2048
#define NTOK (B2*T)               /* 16384 */
#define NELEM ((size_t)NTOK*DD)   /* 8388608 */

// ---------------- fp32 scratch ----------------
#define OFF_XN ((size_t)0)
#define OFF_TN (OFF_XN + NELEM)
#define OFF_Q  (OFF_TN + NELEM)   // head layout [b,h,n,dh]
#define OFF_K  (OFF_Q  + NELEM)
#define OFF_V  (OFF_K  + NELEM)
#define OFF_Y  (OFF_V  + NELEM)   // [b,n,D]
#define OFF_HS (OFF_Y  + NELEM)
#define OFF_S  (OFF_HS + NELEM)   // scores [bh,n,m]
#define OFF_SS (OFF_S  + (size_t)B2*H*T*T)
#define SCRATCH_TOTAL (OFF_SS + (size_t)B2*2*DD)

__device__ __align__(16) float g_scratch[SCRATCH_TOTAL];
__device__ __align__(16) float g_wt[4 * (size_t)DD * DD];   // transposed weights [n][k], tf32-rounded

// ---------------- tf32 helpers ----------------
__device__ __forceinline__ uint32_t f2tf32(float x) {
    uint32_t r;
    asm("cvt.rna.tf32.f32 %0, %1;" : "=r"(r) : "f"(x));
    return r;
}
__device__ __forceinline__ float rnd_tf32(float x) { return __uint_as_float(f2tf32(x)); }

// m16n8k8 tf32 MMA: A row-major (4 regs), B col-major (2 regs), C fp32 (4 regs)
__device__ __forceinline__ void mma8(float* c, const uint32_t* a, const uint32_t* b) {
    asm volatile(
        "mma.sync.aligned.m16n8k8.row.col.f32.tf32.tf32.f32 "
        "{%0,%1,%2,%3},{%4,%5,%6,%7},{%8,%9},{%0,%1,%2,%3};\n"
        : "+f"(c[0]), "+f"(c[1]), "+f"(c[2]), "+f"(c[3])
        : "r"(a[0]), "r"(a[1]), "r"(a[2]), "r"(a[3]), "r"(b[0]), "r"(b[1]));
}

// ================= weight transpose + tf32 round: Wt[n][k] = rnd(W[k][n]) =================
__global__ void wtrans_kernel(const float* __restrict__ W, int widx) {
    __shared__ float t[32][33];
    float* Wt = g_wt + (size_t)widx * DD * DD;
    int nb = blockIdx.x * 32, kb = blockIdx.y * 32;
    int tx = threadIdx.x, ty = threadIdx.y;   // 32 x 8
    #pragma unroll
    for (int i = ty; i < 32; i += 8)
        t[i][tx] = W[(size_t)(kb + i) * DD + nb + tx];
    __syncthreads();
    #pragma unroll
    for (int i = ty; i < 32; i += 8)
        Wt[(size_t)(nb + i) * DD + kb + tx] = rnd_tf32(t[tx][i]);
}

// ================= LayerNorm -> tf32-rounded fp32 (xn from xa, tn from xb) =================
__global__ void ln_kernel(const float* __restrict__ x1, const float* __restrict__ x2,
                          const float* __restrict__ gx, const float* __restrict__ bx,
                          const float* __restrict__ gt, const float* __restrict__ bt) {
    int rid = blockIdx.x;              // 0 .. 2*NTOK-1
    bool is_t = rid >= NTOK;
    int r = is_t ? rid - NTOK : rid;
    const float* src;
    if (!is_t) src = (r < NTOK/2) ? x1 + (size_t)r*DD : x2 + (size_t)(r - NTOK/2)*DD;
    else       src = (r < NTOK/2) ? x2 + (size_t)r*DD : x1 + (size_t)(r - NTOK/2)*DD;
    float* dst = g_scratch + (is_t ? OFF_TN : OFF_XN) + (size_t)r*DD;
    const float* g  = is_t ? gt : gx;
    const float* be = is_t ? bt : bx;

    int tid = threadIdx.x;             // 128 threads, 4 floats each
    float4 v = ((const float4*)src)[tid];
    float s  = v.x + v.y + v.z + v.w;
    float sq = v.x*v.x + v.y*v.y + v.z*v.z + v.w*v.w;

    __shared__ float red[2][4];
    #pragma unroll
    for (int o = 16; o; o >>= 1) {
        s  += __shfl_xor_sync(0xffffffffu, s,  o);
        sq += __shfl_xor_sync(0xffffffffu, sq, o);
    }
    if ((tid & 31) == 0) { red[0][tid>>5] = s; red[1][tid>>5] = sq; }
    __syncthreads();
    s  = red[0][0] + red[0][1] + red[0][2] + red[0][3];
    sq = red[1][0] + red[1][1] + red[1][2] + red[1][3];
    float mean = s * (1.0f/DD);
    float var  = sq * (1.0f/DD) - mean*mean;
    float inv  = rsqrtf(var + 1e-5f);

    float4 gg = ((const float4*)g)[tid];
    float4 bb = ((const float4*)be)[tid];
    float4 o;
    o.x = rnd_tf32((v.x-mean)*inv*gg.x + bb.x);
    o.y = rnd_tf32((v.y-mean)*inv*gg.y + bb.y);
    o.z = rnd_tf32((v.z-mean)*inv*gg.z + bb.z);
    o.w = rnd_tf32((v.w-mean)*inv*gg.w + bb.w);
    ((float4*)dst)[tid] = o;
}

// ================= tf32 MMA GEMM: C[M,N] = A[M,K] @ Wt[N,K]^T + bias =================
// 128x128 block tile, BK=32, 256 threads (8 warps: 2 m x 4 n), warp tile 64x32.
// SEL 0: A=XN -> Q (head layout, rounded); 1: A=TN -> K; 2: A=TN -> V;
// SEL 3: A=HS -> out (+bias +residual xa, full fp32)
template<int SEL>
__global__ void __launch_bounds__(256)
mma_gemm(int widx, const float* __restrict__ bias,
         const float* __restrict__ x1, const float* __restrict__ x2,
         float* __restrict__ outp) {
    const float* A = g_scratch + (SEL == 0 ? OFF_XN : (SEL == 3 ? OFF_HS : OFF_TN));
    const float* Wt = g_wt + (size_t)widx * DD * DD;
    __shared__ float As[128*32];
    __shared__ float Bs[128*32];
    int tid = threadIdx.x, lane = tid & 31, wid = tid >> 5;
    int wm = wid >> 2, wn = wid & 3;
    int gid = lane >> 2, tig = lane & 3;
    int m0 = blockIdx.y * 128, n0 = blockIdx.x * 128;
    float c[4][4][4] = {};
    int r4 = tid >> 3, kc = (tid & 7) * 4;
    int sx = gid << 2;

    for (int k0 = 0; k0 < DD; k0 += 32) {
        #pragma unroll
        for (int p = 0; p < 4; p++) {
            int row = r4 + p * 32;
            int kx = kc ^ ((row & 7) << 2);
            *(float4*)(As + row*32 + kx) = *(const float4*)(A  + (size_t)(m0+row)*DD + k0 + kc);
            *(float4*)(Bs + row*32 + kx) = *(const float4*)(Wt + (size_t)(n0+row)*DD + k0 + kc);
        }
        __syncthreads();
        const uint32_t* Au = (const uint32_t*)As;
        const uint32_t* Bu = (const uint32_t*)Bs;
        #pragma unroll
        for (int ks = 0; ks < 4; ks++) {
            int kk = ks * 8;
            int c0 = (kk + tig) ^ sx;
            int c1 = (kk + tig + 4) ^ sx;
            uint32_t a[4][4];
            #pragma unroll
            for (int mi = 0; mi < 4; mi++) {
                int rm = (wm*64 + mi*16 + gid) * 32;
                a[mi][0] = Au[rm + c0];
                a[mi][1] = Au[rm + 8*32 + c0];
                a[mi][2] = Au[rm + c1];
                a[mi][3] = Au[rm + 8*32 + c1];
            }
            uint32_t b[4][2];
            #pragma unroll
            for (int ni = 0; ni < 4; ni++) {
                int rn = (wn*32 + ni*8 + gid) * 32;
                b[ni][0] = Bu[rn + c0];
                b[ni][1] = Bu[rn + c1];
            }
            #pragma unroll
            for (int mi = 0; mi < 4; mi++)
                #pragma unroll
                for (int ni = 0; ni < 4; ni++)
                    mma8(c[mi][ni], a[mi], b[ni]);
        }
        __syncthreads();
    }

    #pragma unroll
    for (int mi = 0; mi < 4; mi++) {
        #pragma unroll
        for (int ni = 0; ni < 4; ni++) {
            #pragma unroll
            for (int r = 0; r < 4; r++) {
                int m = m0 + wm*64 + mi*16 + gid + ((r >= 2) ? 8 : 0);
                int n = n0 + wn*32 + ni*8 + 2*tig + (r & 1);
                float v = c[mi][ni][r] + bias[n];
                if (SEL < 3) {
                    int b_ = m >> 9, nn = m & 511, h = n >> 6, d = n & 63;
                    float* C = g_scratch + (SEL == 0 ? OFF_Q : (SEL == 1 ? OFF_K : OFF_V));
                    C[(((size_t)(b_*H + h)*T + nn)*DH) + d] = rnd_tf32(v);
                } else {
                    const float* src = (m < NTOK/2) ? x1 + (size_t)m*DD
                                                    : x2 + (size_t)(m - NTOK/2)*DD;
                    outp[(size_t)m*DD + n] = v + src[n];
                }
            }
        }
    }
}

// ================= scores: S[bh,n,m] = Q_h[n,:]·K_h[m,:]/8 + mask  (tf32 MMA) =================
// 64x64 output tile, 256 threads (8 warps: 2 x 4), warp tile 32x16.
__global__ void __launch_bounds__(256)
scores_mma(const float* __restrict__ mask) {
    __shared__ float Qs[64*64];
    __shared__ float Ks[64*64];
    int bh = blockIdx.z, b = bh >> 3;
    const float* Q = g_scratch + OFF_Q + (size_t)bh*T*DH;
    const float* K = g_scratch + OFF_K + (size_t)bh*T*DH;
    int n0 = blockIdx.y * 64, m0 = blockIdx.x * 64;
    int tid = threadIdx.x, lane = tid & 31, wid = tid >> 5;
    int wm = wid >> 2, wn = wid & 3;
    int gid = lane >> 2, tig = lane & 3;
    int sx = gid << 2;

    int r16 = tid >> 4, dc = (tid & 15) * 4;
    #pragma unroll
    for (int p = 0; p < 4; p++) {
        int row = r16 + p * 16;
        int dx = dc ^ ((row & 7) << 2);
        *(float4*)(Qs + row*64 + dx) = *(const float4*)(Q + (size_t)(n0+row)*DH + dc);
        *(float4*)(Ks + row*64 + dx) = *(const float4*)(K + (size_t)(m0+row)*DH + dc);
    }
    __syncthreads();

    const uint32_t* Qu = (const uint32_t*)Qs;
    const uint32_t* Ku = (const uint32_t*)Ks;
    float c[2][2][4] = {};
    #pragma unroll
    for (int ks = 0; ks < 8; ks++) {
        int kk = ks * 8;
        int c0 = (kk + tig) ^ sx;
        int c1 = (kk + tig + 4) ^ sx;
        uint32_t a[2][4], bf[2][2];
        #pragma unroll
        for (int mi = 0; mi < 2; mi++) {
            int rm = (wm*32 + mi*16 + gid) * 64;
            a[mi][0] = Qu[rm + c0];
            a[mi][1] = Qu[rm + 8*64 + c0];
            a[mi][2] = Qu[rm + c1];
            a[mi][3] = Qu[rm + 8*64 + c1];
        }
        #pragma unroll
        for (int ni = 0; ni < 2; ni++) {
            int rn = (wn*16 + ni*8 + gid) * 64;
            bf[ni][0] = Ku[rn + c0];
            bf[ni][1] = Ku[rn + c1];
        }
        #pragma unroll
        for (int mi = 0; mi < 2; mi++)
            #pragma unroll
            for (int ni = 0; ni < 2; ni++)
                mma8(c[mi][ni], a[mi], bf[ni]);
    }

    float* S = g_scratch + OFF_S + (size_t)bh*T*T;
    #pragma unroll
    for (int mi = 0; mi < 2; mi++)
        #pragma unroll
        for (int ni = 0; ni < 2; ni++)
            #pragma unroll
            for (int r = 0; r < 4; r++) {
                int n = n0 + wm*32 + mi*16 + gid + ((r >= 2) ? 8 : 0);
                int m = m0 + wn*16 + ni*8 + 2*tig + (r & 1);
                float mv = mask[((size_t)b*T + n)*T + m];
                S[(size_t)n*T + m] = c[mi][ni][r]*0.125f + (1.0f - mv)*(-100000.0f);
            }
}

// ================= row softmax (writes tf32-rounded weights) =================
__global__ void softmax_kernel() {
    float* row = g_scratch + OFF_S + (size_t)blockIdx.x * T;
    int tid = threadIdx.x;
    float4 v = ((const float4*)row)[tid];

    __shared__ float red[4];
    float mx = fmaxf(fmaxf(v.x, v.y), fmaxf(v.z, v.w));
    #pragma unroll
    for (int o = 16; o; o >>= 1) mx = fmaxf(mx, __shfl_xor_sync(0xffffffffu, mx, o));
    if ((tid & 31) == 0) red[tid >> 5] = mx;
    __syncthreads();
    mx = fmaxf(fmaxf(red[0], red[1]), fmaxf(red[2], red[3]));
    __syncthreads();

    float4 e;
    e.x = expf(v.x - mx); e.y = expf(v.y - mx);
    e.z = expf(v.z - mx); e.w = expf(v.w - mx);
    float s = e.x + e.y + e.z + e.w;
    #pragma unroll
    for (int o = 16; o; o >>= 1) s += __shfl_xor_sync(0xffffffffu, s, o);
    if ((tid & 31) == 0) red[tid >> 5] = s;
    __syncthreads();
    s = red[0] + red[1] + red[2] + red[3];
    float inv = 1.0f / s;
    float4 o;
    o.x = rnd_tf32(e.x * inv); o.y = rnd_tf32(e.y * inv);
    o.z = rnd_tf32(e.z * inv); o.w = rnd_tf32(e.w * inv);
    ((float4*)row)[tid] = o;
}

// ================= Y[n,dh] = S[n,:] @ V[:,dh]  (tf32 MMA) =================
// 64(n) x 64(dh) tile, K=512 over m, BK=32; 8 warps (2 x 4), warp tile 32x16.
__global__ void __launch_bounds__(256)
av_mma() {
    __shared__ float Ws[64*32];
    __shared__ float Vs[32*64];
    int bh = blockIdx.y, b = bh >> 3, h = bh & 7;
    const float* S = g_scratch + OFF_S + (size_t)bh*T*T;
    const float* V = g_scratch + OFF_V + (size_t)bh*T*DH;
    int n0 = blockIdx.x * 64;
    int tid = threadIdx.x, lane = tid & 31, wid = tid >> 5;
    int wm = wid >> 2, wn = wid & 3;
    int gid = lane >> 2, tig = lane & 3;
    int sx = gid << 2;
    float c[2][2][4] = {};

    int rw = tid >> 3, kcw = (tid & 7) * 4;   // Ws: 64 rows x 8 f4
    int rv = tid >> 4, dcv = (tid & 15) * 4;  // Vs: 32 rows x 16 f4

    for (int k0 = 0; k0 < T; k0 += 32) {
        #pragma unroll
        for (int p = 0; p < 2; p++) {
            int row = rw + p * 32;
            int kx = kcw ^ ((row & 7) << 2);
            *(float4*)(Ws + row*32 + kx) = *(const float4*)(S + (size_t)(n0+row)*T + k0 + kcw);
            int vrow = rv + p * 16;
            int dx = dcv ^ ((vrow & 7) << 3);
            *(float4*)(Vs + vrow*64 + dx) = *(const float4*)(V + (size_t)(k0+vrow)*DH + dcv);
        }
        __syncthreads();
        const uint32_t* Wu = (const uint32_t*)Ws;
        const uint32_t* Vu = (const uint32_t*)Vs;
        #pragma unroll
        for (int ks = 0; ks < 4; ks++) {
            int kk = ks * 8;
            int c0 = (kk + tig) ^ sx;
            int c1 = (kk + tig + 4) ^ sx;
            uint32_t a[2][4];
            #pragma unroll
            for (int mi = 0; mi < 2; mi++) {
                int rm = (wm*32 + mi*16 + gid) * 32;
                a[mi][0] = Wu[rm + c0];
                a[mi][1] = Wu[rm + 8*32 + c0];
                a[mi][2] = Wu[rm + c1];
                a[mi][3] = Wu[rm + 8*32 + c1];
            }
            uint32_t bf[2][2];
            int k_lo = kk + tig, k_hi = kk + tig + 4;
            #pragma unroll
            for (int ni = 0; ni < 2; ni++) {
                int cn = wn*16 + ni*8 + gid;
                bf[ni][0] = Vu[k_lo*64 + (cn ^ ((k_lo & 7) << 3))];
                bf[ni][1] = Vu[k_hi*64 + (cn ^ ((k_hi & 7) << 3))];
            }
            #pragma unroll
            for (int mi = 0; mi < 2; mi++)
                #pragma unroll
                for (int ni = 0; ni < 2; ni++)
                    mma8(c[mi][ni], a[mi], bf[ni]);
        }
        __syncthreads();
    }

    float* Y = g_scratch + OFF_Y;
    #pragma unroll
    for (int mi = 0; mi < 2; mi++)
        #pragma unroll
        for (int ni = 0; ni < 2; ni++)
            #pragma unroll
            for (int r = 0; r < 4; r++) {
                int n = n0 + wm*32 + mi*16 + gid + ((r >= 2) ? 8 : 0);
                int d = wn*16 + ni*8 + 2*tig + (r & 1);
                Y[((size_t)b*T + n)*DD + h*DH + d] = c[mi][ni][r];
            }
}

// ================= emb FiLM params (fp32) =================
__global__ void emb_kernel(const float* __restrict__ emb, const float* __restrict__ Wemb,
                           const float* __restrict__ bemb) {
    int b   = blockIdx.x >> 2;
    int col = (blockIdx.x & 3) * 256 + threadIdx.x;
    __shared__ float se[256];
    float acc = 0.0f;
    for (int kc = 0; kc < TE; kc += 256) {
        float e = emb[(size_t)b*TE + kc + threadIdx.x];
        se[threadIdx.x] = e / (1.0f + expf(-e));
        __syncthreads();
        #pragma unroll 8
        for (int kk = 0; kk < 256; kk++)
            acc += se[kk] * Wemb[(size_t)(kc + kk)*(2*DD) + col];
        __syncthreads();
    }
    g_scratch[OFF_SS + (size_t)b*(2*DD) + col] = acc + bemb[col];
}

// ================= hs = silu( LN(y)*(1+scale) + shift ), tf32-rounded =================
__global__ void film_kernel(const float* __restrict__ sbg, const float* __restrict__ sbb) {
    int r = blockIdx.x;
    int b = r >> 9;
    const float* y = g_scratch + OFF_Y + (size_t)r*DD;
    float* dst = g_scratch + OFF_HS + (size_t)r*DD;
    const float* ss = g_scratch + OFF_SS + (size_t)b*(2*DD);

    int tid = threadIdx.x;
    float4 v = ((const float4*)y)[tid];
    float s  = v.x + v.y + v.z + v.w;
    float sq = v.x*v.x + v.y*v.y + v.z*v.z + v.w*v.w;
    __shared__ float red[2][4];
    #pragma unroll
    for (int o = 16; o; o >>= 1) {
        s  += __shfl_xor_sync(0xffffffffu, s,  o);
        sq += __shfl_xor_sync(0xffffffffu, sq, o);
    }
    if ((tid & 31) == 0) { red[0][tid>>5] = s; red[1][tid>>5] = sq; }
    __syncthreads();
    s  = red[0][0] + red[0][1] + red[0][2] + red[0][3];
    sq = red[1][0] + red[1][1] + red[1][2] + red[1][3];
    float mean = s * (1.0f/DD);
    float var  = sq * (1.0f/DD) - mean*mean;
    float inv  = rsqrtf(var + 1e-5f);

    int col = tid * 4;
    float vv[4] = {v.x, v.y, v.z, v.w};
    float4 o;
    float* op = &o.x;
    #pragma unroll
    for (int cc = 0; cc < 4; cc++) {
        float ln = (vv[cc] - mean) * inv * sbg[col + cc] + sbb[col + cc];
        float hh = ln * (1.0f + ss[col + cc]) + ss[512 + col + cc];
        op[cc] = rnd_tf32(hh / (1.0f + expf(-hh)));
    }
    ((float4*)dst)[tid] = o;
}

// ================= launch =================
extern "C" void kernel_launch(void* const* d_in, const int* in_sizes, int n_in,
                              void* d_out, int out_size) {
    const float* x1    = (const float*)d_in[0];
    const float* x2    = (const float*)d_in[1];
    const float* emb   = (const float*)d_in[2];
    const float* mask  = (const float*)d_in[3];
    const float* ln_x_g = (const float*)d_in[4];
    const float* ln_x_b = (const float*)d_in[5];
    const float* ln_t_g = (const float*)d_in[6];
    const float* ln_t_b = (const float*)d_in[7];
    const float* Wq = (const float*)d_in[8];
    const float* bq = (const float*)d_in[9];
    const float* Wk = (const float*)d_in[10];
    const float* bk = (const float*)d_in[11];
    const float* Wv = (const float*)d_in[12];
    const float* bv = (const float*)d_in[13];
    const float* Wemb = (const float*)d_in[14];
    const float* bemb = (const float*)d_in[15];
    const float* sb_g = (const float*)d_in[16];
    const float* sb_b = (const float*)d_in[17];
    const float* Wout = (const float*)d_in[18];
    const float* bout = (const float*)d_in[19];
    float* out = (float*)d_out;

    dim3 tb(32, 8), tg(16, 16);
    wtrans_kernel<<<tg, tb>>>(Wq, 0);
    wtrans_kernel<<<tg, tb>>>(Wk, 1);
    wtrans_kernel<<<tg, tb>>>(Wv, 2);
    wtrans_kernel<<<tg, tb>>>(Wout, 3);

    ln_kernel<<<2*NTOK, 128>>>(x1, x2, ln_x_g, ln_x_b, ln_t_g, ln_t_b);

    dim3 gg(DD/128, NTOK/128);   // (4, 128)
    mma_gemm<0><<<gg, 256>>>(0, bq, x1, x2, nullptr);
    mma_gemm<1><<<gg, 256>>>(1, bk, x1, x2, nullptr);
    mma_gemm<2><<<gg, 256>>>(2, bv, x1, x2, nullptr);

    emb_kernel<<<B2*4, 256>>>(emb, Wemb, bemb);

    scores_mma<<<dim3(T/64, T/64, B2*H), 256>>>(mask);
    softmax_kernel<<<B2*H*T, 128>>>();
    av_mma<<<dim3(T/64, B2*H), 256>>>();

    film_kernel<<<NTOK, 128>>>(sb_g, sb_b);
    mma_gemm<3><<<gg, 256>>>(3, bout, x1, x2, out);
}

// round 5
// speedup vs baseline: 2.9526x; 1.4161x over previous
#include <cuda_runtime.h>
#include <math.h>
#include <stdint.h>

#define B2   32
#define T    512
#define DD   512
#define H    8
#define DH   64
#define TE   2048
#define NTOK (B2*T)               /* 16384 */
#define NELEM ((size_t)NTOK*DD)   /* 8388608 */

// ---------------- fp32 scratch ----------------
#define OFF_XN ((size_t)0)
#define OFF_TN (OFF_XN + NELEM)
#define OFF_Q  (OFF_TN + NELEM)   // head layout [b,h,n,dh]
#define OFF_K  (OFF_Q  + NELEM)
#define OFF_V  (OFF_K  + NELEM)
#define OFF_Y  (OFF_V  + NELEM)   // [b,n,D]
#define OFF_HS (OFF_Y  + NELEM)
#define OFF_SS (OFF_HS + NELEM)
#define SCRATCH_TOTAL (OFF_SS + (size_t)B2*2*DD)

__device__ __align__(16) float g_scratch[SCRATCH_TOTAL];
__device__ __align__(16) float g_wt[4 * (size_t)DD * DD];   // transposed weights [n][k], tf32-rounded

// ---------------- helpers ----------------
__device__ __forceinline__ uint32_t f2tf32(float x) {
    uint32_t r;
    asm("cvt.rna.tf32.f32 %0, %1;" : "=r"(r) : "f"(x));
    return r;
}
__device__ __forceinline__ float rnd_tf32(float x) { return __uint_as_float(f2tf32(x)); }

__device__ __forceinline__ void mma8(float* c, const uint32_t* a, const uint32_t* b) {
    asm volatile(
        "mma.sync.aligned.m16n8k8.row.col.f32.tf32.tf32.f32 "
        "{%0,%1,%2,%3},{%4,%5,%6,%7},{%8,%9},{%0,%1,%2,%3};\n"
        : "+f"(c[0]), "+f"(c[1]), "+f"(c[2]), "+f"(c[3])
        : "r"(a[0]), "r"(a[1]), "r"(a[2]), "r"(a[3]), "r"(b[0]), "r"(b[1]));
}

__device__ __forceinline__ uint32_t smem_u32(const void* p) {
    uint32_t a;
    asm("{ .reg .u64 t; cvta.to.shared.u64 t, %1; cvt.u32.u64 %0, t; }" : "=r"(a) : "l"(p));
    return a;
}
__device__ __forceinline__ void cp16(uint32_t d, const void* s) {
    asm volatile("cp.async.cg.shared.global [%0], [%1], 16;\n" :: "r"(d), "l"(s));
}
__device__ __forceinline__ void cp_commit() {
    asm volatile("cp.async.commit_group;\n" ::: "memory");
}
__device__ __forceinline__ void cp_wait1() {
    asm volatile("cp.async.wait_group 1;\n" ::: "memory");
}
__device__ __forceinline__ void cp_wait0() {
    asm volatile("cp.async.wait_group 0;\n" ::: "memory");
}

// ================= 4-in-1 weight transpose + tf32 round =================
__global__ void wtrans4_kernel(const float* __restrict__ W0, const float* __restrict__ W1,
                               const float* __restrict__ W2, const float* __restrict__ W3) {
    __shared__ float t[32][33];
    int wi = blockIdx.z;
    const float* W = (wi == 0) ? W0 : (wi == 1) ? W1 : (wi == 2) ? W2 : W3;
    float* Wt = g_wt + (size_t)wi * DD * DD;
    int nb = blockIdx.x * 32, kb = blockIdx.y * 32;
    int tx = threadIdx.x, ty = threadIdx.y;   // 32 x 8
    #pragma unroll
    for (int i = ty; i < 32; i += 8)
        t[i][tx] = W[(size_t)(kb + i) * DD + nb + tx];
    __syncthreads();
    #pragma unroll
    for (int i = ty; i < 32; i += 8)
        Wt[(size_t)(nb + i) * DD + kb + tx] = rnd_tf32(t[tx][i]);
}

// ================= fused LayerNorm: one block handles x1[r] & x2[r], writes 4 rows =================
__global__ void ln2_kernel(const float* __restrict__ x1, const float* __restrict__ x2,
                           const float* __restrict__ gx, const float* __restrict__ bx,
                           const float* __restrict__ gt, const float* __restrict__ bt) {
    int r = blockIdx.x;                // 0..NTOK/2-1
    int tid = threadIdx.x;             // 128 threads, 4 floats each
    float4 v1 = ((const float4*)(x1 + (size_t)r*DD))[tid];
    float4 v2 = ((const float4*)(x2 + (size_t)r*DD))[tid];

    float s1 = v1.x+v1.y+v1.z+v1.w, q1 = v1.x*v1.x+v1.y*v1.y+v1.z*v1.z+v1.w*v1.w;
    float s2 = v2.x+v2.y+v2.z+v2.w, q2 = v2.x*v2.x+v2.y*v2.y+v2.z*v2.z+v2.w*v2.w;

    __shared__ float red[4][4];
    #pragma unroll
    for (int o = 16; o; o >>= 1) {
        s1 += __shfl_xor_sync(0xffffffffu, s1, o);
        q1 += __shfl_xor_sync(0xffffffffu, q1, o);
        s2 += __shfl_xor_sync(0xffffffffu, s2, o);
        q2 += __shfl_xor_sync(0xffffffffu, q2, o);
    }
    if ((tid & 31) == 0) {
        int w = tid >> 5;
        red[0][w] = s1; red[1][w] = q1; red[2][w] = s2; red[3][w] = q2;
    }
    __syncthreads();
    s1 = red[0][0]+red[0][1]+red[0][2]+red[0][3];
    q1 = red[1][0]+red[1][1]+red[1][2]+red[1][3];
    s2 = red[2][0]+red[2][1]+red[2][2]+red[2][3];
    q2 = red[3][0]+red[3][1]+red[3][2]+red[3][3];
    float m1 = s1*(1.0f/DD), iv1 = rsqrtf(q1*(1.0f/DD) - m1*m1 + 1e-5f);
    float m2 = s2*(1.0f/DD), iv2 = rsqrtf(q2*(1.0f/DD) - m2*m2 + 1e-5f);

    float4 ggx = ((const float4*)gx)[tid], bbx = ((const float4*)bx)[tid];
    float4 ggt = ((const float4*)gt)[tid], bbt = ((const float4*)bt)[tid];

    float n1[4] = {(v1.x-m1)*iv1, (v1.y-m1)*iv1, (v1.z-m1)*iv1, (v1.w-m1)*iv1};
    float n2[4] = {(v2.x-m2)*iv2, (v2.y-m2)*iv2, (v2.z-m2)*iv2, (v2.w-m2)*iv2};
    const float* gxp = &ggx.x; const float* bxp = &bbx.x;
    const float* gtp = &ggt.x; const float* btp = &bbt.x;

    float4 o;
    float* op = &o.x;
    float* XN = g_scratch + OFF_XN;
    float* TN = g_scratch + OFF_TN;
    const int half = NTOK/2;

    #pragma unroll
    for (int c = 0; c < 4; c++) op[c] = rnd_tf32(n1[c]*gxp[c] + bxp[c]);
    ((float4*)(XN + (size_t)r*DD))[tid] = o;
    #pragma unroll
    for (int c = 0; c < 4; c++) op[c] = rnd_tf32(n2[c]*gxp[c] + bxp[c]);
    ((float4*)(XN + (size_t)(r+half)*DD))[tid] = o;
    #pragma unroll
    for (int c = 0; c < 4; c++) op[c] = rnd_tf32(n2[c]*gtp[c] + btp[c]);
    ((float4*)(TN + (size_t)r*DD))[tid] = o;
    #pragma unroll
    for (int c = 0; c < 4; c++) op[c] = rnd_tf32(n1[c]*gtp[c] + btp[c]);
    ((float4*)(TN + (size_t)(r+half)*DD))[tid] = o;
}

// ================= pipelined tf32 MMA GEMM: C[M,N] = A[M,K] @ Wt[N,K]^T + bias =================
// 128x128 tile, BK=32, 2-stage cp.async, 256 threads (8 warps, 2m x 4n), warp tile 64x32.
template<int SEL>
__global__ void __launch_bounds__(256)
mma_gemm(int widx, const float* __restrict__ bias,
         const float* __restrict__ x1, const float* __restrict__ x2,
         float* __restrict__ outp) {
    const float* A = g_scratch + (SEL == 0 ? OFF_XN : (SEL == 3 ? OFF_HS : OFF_TN));
    const float* Wt = g_wt + (size_t)widx * DD * DD;
    extern __shared__ float dsm[];
    float* As = dsm;            // 2 stages x 4096 floats
    float* Bs = dsm + 8192;     // 2 stages x 4096 floats
    uint32_t a_base = smem_u32(As), b_base = smem_u32(Bs);

    int tid = threadIdx.x, lane = tid & 31, wid = tid >> 5;
    int wm = wid >> 2, wn = wid & 3;
    int gid = lane >> 2, tig = lane & 3;
    int m0 = blockIdx.y * 128, n0 = blockIdx.x * 128;
    float c[4][4][4] = {};
    int r4 = tid >> 3, kc = (tid & 7) * 4;
    int sx = gid << 2;

    // prologue: stage 0
    #pragma unroll
    for (int p = 0; p < 4; p++) {
        int row = r4 + p * 32;
        int kx = kc ^ ((row & 7) << 2);
        cp16(a_base + (uint32_t)(row*32 + kx)*4, A  + (size_t)(m0+row)*DD + kc);
        cp16(b_base + (uint32_t)(row*32 + kx)*4, Wt + (size_t)(n0+row)*DD + kc);
    }
    cp_commit();

    for (int it = 0; it < 16; it++) {
        int st = it & 1;
        if (it < 15) {
            int k0 = (it + 1) * 32;
            int so = (st ^ 1) * 4096;
            #pragma unroll
            for (int p = 0; p < 4; p++) {
                int row = r4 + p * 32;
                int kx = kc ^ ((row & 7) << 2);
                cp16(a_base + (uint32_t)(so + row*32 + kx)*4, A  + (size_t)(m0+row)*DD + k0 + kc);
                cp16(b_base + (uint32_t)(so + row*32 + kx)*4, Wt + (size_t)(n0+row)*DD + k0 + kc);
            }
        }
        cp_commit();
        if (it < 15) cp_wait1(); else cp_wait0();
        __syncthreads();

        const uint32_t* Au = (const uint32_t*)(As + st*4096);
        const uint32_t* Bu = (const uint32_t*)(Bs + st*4096);
        #pragma unroll
        for (int ks = 0; ks < 4; ks++) {
            int kk = ks * 8;
            int c0 = (kk + tig) ^ sx;
            int c1 = (kk + tig + 4) ^ sx;
            uint32_t a[4][4];
            #pragma unroll
            for (int mi = 0; mi < 4; mi++) {
                int rm = (wm*64 + mi*16 + gid) * 32;
                a[mi][0] = Au[rm + c0];
                a[mi][1] = Au[rm + 8*32 + c0];
                a[mi][2] = Au[rm + c1];
                a[mi][3] = Au[rm + 8*32 + c1];
            }
            uint32_t b[4][2];
            #pragma unroll
            for (int ni = 0; ni < 4; ni++) {
                int rn = (wn*32 + ni*8 + gid) * 32;
                b[ni][0] = Bu[rn + c0];
                b[ni][1] = Bu[rn + c1];
            }
            #pragma unroll
            for (int mi = 0; mi < 4; mi++)
                #pragma unroll
                for (int ni = 0; ni < 4; ni++)
                    mma8(c[mi][ni], a[mi], b[ni]);
        }
        __syncthreads();
    }

    #pragma unroll
    for (int mi = 0; mi < 4; mi++) {
        #pragma unroll
        for (int ni = 0; ni < 4; ni++) {
            #pragma unroll
            for (int r = 0; r < 4; r++) {
                int m = m0 + wm*64 + mi*16 + gid + ((r >= 2) ? 8 : 0);
                int n = n0 + wn*32 + ni*8 + 2*tig + (r & 1);
                float v = c[mi][ni][r] + bias[n];
                if (SEL < 3) {
                    int b_ = m >> 9, nn = m & 511, h = n >> 6, d = n & 63;
                    float* C = g_scratch + (SEL == 0 ? OFF_Q : (SEL == 1 ? OFF_K : OFF_V));
                    C[(((size_t)(b_*H + h)*T + nn)*DH) + d] = rnd_tf32(v);
                } else {
                    const float* src = (m < NTOK/2) ? x1 + (size_t)m*DD
                                                    : x2 + (size_t)(m - NTOK/2)*DD;
                    outp[(size_t)m*DD + n] = v + src[n];
                }
            }
        }
    }
}

// ================= fused flash attention: scores + online softmax + P@V =================
// Block = 64 q-rows of one (b,h). 4 warps x 16 rows. BC=64 keys per iteration.
// smem (floats): sQ[4096] sK[4096] sV[4096] sP[4096] sM[4096]  = 80KB
__global__ void __launch_bounds__(128)
fa_kernel(const float* __restrict__ mask) {
    extern __shared__ float dsm[];
    float* sQ = dsm;
    float* sK = dsm + 4096;
    float* sV = dsm + 8192;
    float* sP = dsm + 12288;
    float* sM = dsm + 16384;

    int bh = blockIdx.y, b = bh >> 3, h = bh & 7;
    int n0 = blockIdx.x * 64;
    const float* Q = g_scratch + OFF_Q + (size_t)bh*T*DH;
    const float* K = g_scratch + OFF_K + (size_t)bh*T*DH;
    const float* V = g_scratch + OFF_V + (size_t)bh*T*DH;

    int tid = threadIdx.x, lane = tid & 31, w = tid >> 5;
    int gid = lane >> 2, tig = lane & 3;
    int sx = gid << 2;
    int w16 = w * 16;

    // load Q tile (64 x 64), swizzle <<2
    int lr = tid >> 4;             // 0..7
    int lc4 = (tid & 15) * 4;      // 0..60
    #pragma unroll
    for (int p = 0; p < 8; p++) {
        int row = lr + p * 8;
        int cx = lc4 ^ ((row & 7) << 2);
        *(float4*)(sQ + row*64 + cx) = *(const float4*)(Q + (size_t)(n0+row)*DH + lc4);
    }

    float co[8][4] = {};
    float miA = -1e30f, miB = -1e30f;
    float lA = 0.0f, lB = 0.0f;

    for (int mt = 0; mt < T/64; mt++) {
        int m0 = mt * 64;
        __syncthreads();   // previous iteration fully consumed (also orders sQ on mt=0)
        #pragma unroll
        for (int p = 0; p < 8; p++) {
            int row = lr + p * 8;
            int cx2 = lc4 ^ ((row & 7) << 2);
            int cx3 = lc4 ^ ((row & 7) << 3);
            *(float4*)(sK + row*64 + cx2) = *(const float4*)(K + (size_t)(m0+row)*DH + lc4);
            *(float4*)(sV + row*64 + cx3) = *(const float4*)(V + (size_t)(m0+row)*DH + lc4);
            *(float4*)(sM + row*64 + cx2) =
                *(const float4*)(mask + ((size_t)(b*T + n0 + row)*T) + m0 + lc4);
        }
        __syncthreads();

        // S = Q @ K^T  (warp: 16 rows x 64 cols)
        float cs[8][4] = {};
        const uint32_t* Qu = (const uint32_t*)sQ;
        const uint32_t* Ku = (const uint32_t*)sK;
        #pragma unroll
        for (int ks = 0; ks < 8; ks++) {
            int kk = ks * 8;
            int c0 = (kk + tig) ^ sx;
            int c1 = (kk + tig + 4) ^ sx;
            uint32_t a[4];
            int rm = (w16 + gid) * 64;
            a[0] = Qu[rm + c0];
            a[1] = Qu[rm + 8*64 + c0];
            a[2] = Qu[rm + c1];
            a[3] = Qu[rm + 8*64 + c1];
            #pragma unroll
            for (int ni = 0; ni < 8; ni++) {
                int rn = (ni*8 + gid) * 64;
                uint32_t bb[2];
                bb[0] = Ku[rn + c0];
                bb[1] = Ku[rn + c1];
                mma8(cs[ni], a, bb);
            }
        }

        // scale + mask + row max
        float rmA = -1e30f, rmB = -1e30f;
        int rA = w16 + gid, rB = rA + 8;
        #pragma unroll
        for (int ni = 0; ni < 8; ni++) {
            int col = ni*8 + 2*tig;
            float2 mA = *(float2*)(sM + rA*64 + (col ^ sx));
            float2 mB = *(float2*)(sM + rB*64 + (col ^ sx));
            cs[ni][0] = cs[ni][0]*0.125f + (1.0f - mA.x)*(-100000.0f);
            cs[ni][1] = cs[ni][1]*0.125f + (1.0f - mA.y)*(-100000.0f);
            cs[ni][2] = cs[ni][2]*0.125f + (1.0f - mB.x)*(-100000.0f);
            cs[ni][3] = cs[ni][3]*0.125f + (1.0f - mB.y)*(-100000.0f);
            rmA = fmaxf(rmA, fmaxf(cs[ni][0], cs[ni][1]));
            rmB = fmaxf(rmB, fmaxf(cs[ni][2], cs[ni][3]));
        }
        rmA = fmaxf(rmA, __shfl_xor_sync(0xffffffffu, rmA, 1));
        rmA = fmaxf(rmA, __shfl_xor_sync(0xffffffffu, rmA, 2));
        rmB = fmaxf(rmB, __shfl_xor_sync(0xffffffffu, rmB, 1));
        rmB = fmaxf(rmB, __shfl_xor_sync(0xffffffffu, rmB, 2));

        float mnA = fmaxf(miA, rmA), mnB = fmaxf(miB, rmB);
        float alA = __expf(miA - mnA), alB = __expf(miB - mnB);
        miA = mnA; miB = mnB;

        float sumA = 0.0f, sumB = 0.0f;
        #pragma unroll
        for (int ni = 0; ni < 8; ni++) {
            int col = ni*8 + 2*tig;
            float p0 = __expf(cs[ni][0] - mnA);
            float p1 = __expf(cs[ni][1] - mnA);
            float p2 = __expf(cs[ni][2] - mnB);
            float p3 = __expf(cs[ni][3] - mnB);
            sumA += p0 + p1; sumB += p2 + p3;
            float2 pa; pa.x = rnd_tf32(p0); pa.y = rnd_tf32(p1);
            float2 pb; pb.x = rnd_tf32(p2); pb.y = rnd_tf32(p3);
            *(float2*)(sP + rA*64 + (col ^ sx)) = pa;
            *(float2*)(sP + rB*64 + (col ^ sx)) = pb;
        }
        sumA += __shfl_xor_sync(0xffffffffu, sumA, 1);
        sumA += __shfl_xor_sync(0xffffffffu, sumA, 2);
        sumB += __shfl_xor_sync(0xffffffffu, sumB, 1);
        sumB += __shfl_xor_sync(0xffffffffu, sumB, 2);
        lA = lA * alA + sumA;
        lB = lB * alB + sumB;

        #pragma unroll
        for (int ni = 0; ni < 8; ni++) {
            co[ni][0] *= alA; co[ni][1] *= alA;
            co[ni][2] *= alB; co[ni][3] *= alB;
        }
        __syncwarp();

        // O += P @ V  (A = P rows of this warp, B = V[k=m][n=dh])
        const uint32_t* Pu = (const uint32_t*)sP;
        const uint32_t* Vu = (const uint32_t*)sV;
        #pragma unroll
        for (int ks = 0; ks < 8; ks++) {
            int kk = ks * 8;
            int c0 = (kk + tig) ^ sx;
            int c1 = (kk + tig + 4) ^ sx;
            uint32_t a[4];
            int rm = (w16 + gid) * 64;
            a[0] = Pu[rm + c0];
            a[1] = Pu[rm + 8*64 + c0];
            a[2] = Pu[rm + c1];
            a[3] = Pu[rm + 8*64 + c1];
            int klo = kk + tig, khi = kk + tig + 4;
            #pragma unroll
            for (int ni = 0; ni < 8; ni++) {
                int cn = ni*8 + gid;
                uint32_t bb[2];
                bb[0] = Vu[klo*64 + (cn ^ ((klo & 7) << 3))];
                bb[1] = Vu[khi*64 + (cn ^ ((khi & 7) << 3))];
                mma8(co[ni], a, bb);
            }
        }
    }

    // epilogue: normalize + write Y[b,n,D]
    float invA = 1.0f / lA, invB = 1.0f / lB;
    float* Y = g_scratch + OFF_Y;
    int nA = n0 + w16 + gid, nB = nA + 8;
    #pragma unroll
    for (int ni = 0; ni < 8; ni++) {
        int dcol = h*DH + ni*8 + 2*tig;
        float2 oa; oa.x = co[ni][0]*invA; oa.y = co[ni][1]*invA;
        float2 ob; ob.x = co[ni][2]*invB; ob.y = co[ni][3]*invB;
        *(float2*)(Y + ((size_t)(b*T + nA))*DD + dcol) = oa;
        *(float2*)(Y + ((size_t)(b*T + nB))*DD + dcol) = ob;
    }
}

// ================= emb FiLM params (fp32) =================
__global__ void emb_kernel(const float* __restrict__ emb, const float* __restrict__ Wemb,
                           const float* __restrict__ bemb) {
    int b   = blockIdx.x >> 2;
    int col = (blockIdx.x & 3) * 256 + threadIdx.x;
    __shared__ float se[256];
    float acc = 0.0f;
    for (int kc = 0; kc < TE; kc += 256) {
        float e = emb[(size_t)b*TE + kc + threadIdx.x];
        se[threadIdx.x] = e / (1.0f + expf(-e));
        __syncthreads();
        #pragma unroll 8
        for (int kk = 0; kk < 256; kk++)
            acc += se[kk] * Wemb[(size_t)(kc + kk)*(2*DD) + col];
        __syncthreads();
    }
    g_scratch[OFF_SS + (size_t)b*(2*DD) + col] = acc + bemb[col];
}

// ================= hs = silu( LN(y)*(1+scale) + shift ), tf32-rounded =================
__global__ void film_kernel(const float* __restrict__ sbg, const float* __restrict__ sbb) {
    int r = blockIdx.x;
    int b = r >> 9;
    const float* y = g_scratch + OFF_Y + (size_t)r*DD;
    float* dst = g_scratch + OFF_HS + (size_t)r*DD;
    const float* ss = g_scratch + OFF_SS + (size_t)b*(2*DD);

    int tid = threadIdx.x;
    float4 v = ((const float4*)y)[tid];
    float s  = v.x + v.y + v.z + v.w;
    float sq = v.x*v.x + v.y*v.y + v.z*v.z + v.w*v.w;
    __shared__ float red[2][4];
    #pragma unroll
    for (int o = 16; o; o >>= 1) {
        s  += __shfl_xor_sync(0xffffffffu, s,  o);
        sq += __shfl_xor_sync(0xffffffffu, sq, o);
    }
    if ((tid & 31) == 0) { red[0][tid>>5] = s; red[1][tid>>5] = sq; }
    __syncthreads();
    s  = red[0][0] + red[0][1] + red[0][2] + red[0][3];
    sq = red[1][0] + red[1][1] + red[1][2] + red[1][3];
    float mean = s * (1.0f/DD);
    float var  = sq * (1.0f/DD) - mean*mean;
    float inv  = rsqrtf(var + 1e-5f);

    int col = tid * 4;
    float vv[4] = {v.x, v.y, v.z, v.w};
    float4 o;
    float* op = &o.x;
    #pragma unroll
    for (int cc = 0; cc < 4; cc++) {
        float ln = (vv[cc] - mean) * inv * sbg[col + cc] + sbb[col + cc];
        float hh = ln * (1.0f + ss[col + cc]) + ss[512 + col + cc];
        op[cc] = rnd_tf32(hh / (1.0f + expf(-hh)));
    }
    ((float4*)dst)[tid] = o;
}

// ================= launch =================
extern "C" void kernel_launch(void* const* d_in, const int* in_sizes, int n_in,
                              void* d_out, int out_size) {
    const float* x1    = (const float*)d_in[0];
    const float* x2    = (const float*)d_in[1];
    const float* emb   = (const float*)d_in[2];
    const float* mask  = (const float*)d_in[3];
    const float* ln_x_g = (const float*)d_in[4];
    const float* ln_x_b = (const float*)d_in[5];
    const float* ln_t_g = (const float*)d_in[6];
    const float* ln_t_b = (const float*)d_in[7];
    const float* Wq = (const float*)d_in[8];
    const float* bq = (const float*)d_in[9];
    const float* Wk = (const float*)d_in[10];
    const float* bk = (const float*)d_in[11];
    const float* Wv = (const float*)d_in[12];
    const float* bv = (const float*)d_in[13];
    const float* Wemb = (const float*)d_in[14];
    const float* bemb = (const float*)d_in[15];
    const float* sb_g = (const float*)d_in[16];
    const float* sb_b = (const float*)d_in[17];
    const float* Wout = (const float*)d_in[18];
    const float* bout = (const float*)d_in[19];
    float* out = (float*)d_out;

    cudaFuncSetAttribute(mma_gemm<0>, cudaFuncAttributeMaxDynamicSharedMemorySize, 65536);
    cudaFuncSetAttribute(mma_gemm<1>, cudaFuncAttributeMaxDynamicSharedMemorySize, 65536);
    cudaFuncSetAttribute(mma_gemm<2>, cudaFuncAttributeMaxDynamicSharedMemorySize, 65536);
    cudaFuncSetAttribute(mma_gemm<3>, cudaFuncAttributeMaxDynamicSharedMemorySize, 65536);
    cudaFuncSetAttribute(fa_kernel,   cudaFuncAttributeMaxDynamicSharedMemorySize, 81920);

    wtrans4_kernel<<<dim3(16, 16, 4), dim3(32, 8)>>>(Wq, Wk, Wv, Wout);
    ln2_kernel<<<NTOK/2, 128>>>(x1, x2, ln_x_g, ln_x_b, ln_t_g, ln_t_b);

    dim3 gg(DD/128, NTOK/128);   // (4, 128)
    mma_gemm<0><<<gg, 256, 65536>>>(0, bq, x1, x2, nullptr);
    mma_gemm<1><<<gg, 256, 65536>>>(1, bk, x1, x2, nullptr);
    mma_gemm<2><<<gg, 256, 65536>>>(2, bv, x1, x2, nullptr);

    emb_kernel<<<B2*4, 256>>>(emb, Wemb, bemb);

    fa_kernel<<<dim3(T/64, B2*H), 128, 81920>>>(mask);

    film_kernel<<<NTOK, 128>>>(sb_g, sb_b);
    mma_gemm<3><<<gg, 256, 65536>>>(3, bout, x1, x2, out);
}

// round 6
// speedup vs baseline: 3.0359x; 1.0282x over previous
#include <cuda_runtime.h>
#include <math.h>
#include <stdint.h>

#define B2   32
#define T    512
#define DD   512
#define H    8
#define DH   64
#define TE   2048
#define NTOK (B2*T)               /* 16384 */
#define NELEM ((size_t)NTOK*DD)   /* 8388608 */

// ---------------- fp32 scratch ----------------
#define OFF_XN ((size_t)0)
#define OFF_TN (OFF_XN + NELEM)
#define OFF_Q  (OFF_TN + NELEM)   // head layout [b,h,n,dh]
#define OFF_K  (OFF_Q  + NELEM)
#define OFF_V  (OFF_K  + NELEM)
#define OFF_Y  (OFF_V  + NELEM)   // [b,n,D]
#define OFF_HS (OFF_Y  + NELEM)
#define OFF_SS (OFF_HS + NELEM)
#define SCRATCH_TOTAL (OFF_SS + (size_t)B2*2*DD)

__device__ __align__(16) float g_scratch[SCRATCH_TOTAL];
__device__ __align__(16) float g_wt[4 * (size_t)DD * DD];   // transposed weights [n][k], tf32-rounded

// ---------------- helpers ----------------
__device__ __forceinline__ uint32_t f2tf32(float x) {
    uint32_t r;
    asm("cvt.rna.tf32.f32 %0, %1;" : "=r"(r) : "f"(x));
    return r;
}
__device__ __forceinline__ float rnd_tf32(float x) { return __uint_as_float(f2tf32(x)); }

__device__ __forceinline__ void mma8(float* c, const uint32_t* a, const uint32_t* b) {
    asm volatile(
        "mma.sync.aligned.m16n8k8.row.col.f32.tf32.tf32.f32 "
        "{%0,%1,%2,%3},{%4,%5,%6,%7},{%8,%9},{%0,%1,%2,%3};\n"
        : "+f"(c[0]), "+f"(c[1]), "+f"(c[2]), "+f"(c[3])
        : "r"(a[0]), "r"(a[1]), "r"(a[2]), "r"(a[3]), "r"(b[0]), "r"(b[1]));
}

__device__ __forceinline__ uint32_t smem_u32(const void* p) {
    uint32_t a;
    asm("{ .reg .u64 t; cvta.to.shared.u64 t, %1; cvt.u32.u64 %0, t; }" : "=r"(a) : "l"(p));
    return a;
}
__device__ __forceinline__ void cp16(uint32_t d, const void* s) {
    asm volatile("cp.async.cg.shared.global [%0], [%1], 16;\n" :: "r"(d), "l"(s));
}
__device__ __forceinline__ void cp_commit() {
    asm volatile("cp.async.commit_group;\n" ::: "memory");
}
__device__ __forceinline__ void cp_wait1() {
    asm volatile("cp.async.wait_group 1;\n" ::: "memory");
}

// ================= 4-in-1 weight transpose + tf32 round =================
__global__ void wtrans4_kernel(const float* __restrict__ W0, const float* __restrict__ W1,
                               const float* __restrict__ W2, const float* __restrict__ W3) {
    __shared__ float t[32][33];
    int wi = blockIdx.z;
    const float* W = (wi == 0) ? W0 : (wi == 1) ? W1 : (wi == 2) ? W2 : W3;
    float* Wt = g_wt + (size_t)wi * DD * DD;
    int nb = blockIdx.x * 32, kb = blockIdx.y * 32;
    int tx = threadIdx.x, ty = threadIdx.y;   // 32 x 8
    #pragma unroll
    for (int i = ty; i < 32; i += 8)
        t[i][tx] = W[(size_t)(kb + i) * DD + nb + tx];
    __syncthreads();
    #pragma unroll
    for (int i = ty; i < 32; i += 8)
        Wt[(size_t)(nb + i) * DD + kb + tx] = rnd_tf32(t[tx][i]);
}

// ================= fused LayerNorm: one block handles x1[r] & x2[r], writes 4 rows =================
__global__ void ln2_kernel(const float* __restrict__ x1, const float* __restrict__ x2,
                           const float* __restrict__ gx, const float* __restrict__ bx,
                           const float* __restrict__ gt, const float* __restrict__ bt) {
    int r = blockIdx.x;                // 0..NTOK/2-1
    int tid = threadIdx.x;             // 128 threads, 4 floats each
    float4 v1 = ((const float4*)(x1 + (size_t)r*DD))[tid];
    float4 v2 = ((const float4*)(x2 + (size_t)r*DD))[tid];

    float s1 = v1.x+v1.y+v1.z+v1.w, q1 = v1.x*v1.x+v1.y*v1.y+v1.z*v1.z+v1.w*v1.w;
    float s2 = v2.x+v2.y+v2.z+v2.w, q2 = v2.x*v2.x+v2.y*v2.y+v2.z*v2.z+v2.w*v2.w;

    __shared__ float red[4][4];
    #pragma unroll
    for (int o = 16; o; o >>= 1) {
        s1 += __shfl_xor_sync(0xffffffffu, s1, o);
        q1 += __shfl_xor_sync(0xffffffffu, q1, o);
        s2 += __shfl_xor_sync(0xffffffffu, s2, o);
        q2 += __shfl_xor_sync(0xffffffffu, q2, o);
    }
    if ((tid & 31) == 0) {
        int w = tid >> 5;
        red[0][w] = s1; red[1][w] = q1; red[2][w] = s2; red[3][w] = q2;
    }
    __syncthreads();
    s1 = red[0][0]+red[0][1]+red[0][2]+red[0][3];
    q1 = red[1][0]+red[1][1]+red[1][2]+red[1][3];
    s2 = red[2][0]+red[2][1]+red[2][2]+red[2][3];
    q2 = red[3][0]+red[3][1]+red[3][2]+red[3][3];
    float m1 = s1*(1.0f/DD), iv1 = rsqrtf(q1*(1.0f/DD) - m1*m1 + 1e-5f);
    float m2 = s2*(1.0f/DD), iv2 = rsqrtf(q2*(1.0f/DD) - m2*m2 + 1e-5f);

    float4 ggx = ((const float4*)gx)[tid], bbx = ((const float4*)bx)[tid];
    float4 ggt = ((const float4*)gt)[tid], bbt = ((const float4*)bt)[tid];

    float n1[4] = {(v1.x-m1)*iv1, (v1.y-m1)*iv1, (v1.z-m1)*iv1, (v1.w-m1)*iv1};
    float n2[4] = {(v2.x-m2)*iv2, (v2.y-m2)*iv2, (v2.z-m2)*iv2, (v2.w-m2)*iv2};
    const float* gxp = &ggx.x; const float* bxp = &bbx.x;
    const float* gtp = &ggt.x; const float* btp = &bbt.x;

    float4 o;
    float* op = &o.x;
    float* XN = g_scratch + OFF_XN;
    float* TN = g_scratch + OFF_TN;
    const int half = NTOK/2;

    #pragma unroll
    for (int c = 0; c < 4; c++) op[c] = rnd_tf32(n1[c]*gxp[c] + bxp[c]);
    ((float4*)(XN + (size_t)r*DD))[tid] = o;
    #pragma unroll
    for (int c = 0; c < 4; c++) op[c] = rnd_tf32(n2[c]*gxp[c] + bxp[c]);
    ((float4*)(XN + (size_t)(r+half)*DD))[tid] = o;
    #pragma unroll
    for (int c = 0; c < 4; c++) op[c] = rnd_tf32(n2[c]*gtp[c] + btp[c]);
    ((float4*)(TN + (size_t)r*DD))[tid] = o;
    #pragma unroll
    for (int c = 0; c < 4; c++) op[c] = rnd_tf32(n1[c]*gtp[c] + btp[c]);
    ((float4*)(TN + (size_t)(r+half)*DD))[tid] = o;
}

// ================= 3-stage pipelined tf32 MMA GEMM =================
// QKV=true : one launch for Q,K,V. n-global in [0,1536): widx = n>>9 selects weight/A/output.
// QKV=false: out-projection + bias + residual.
// 128x128 tile, BK=32, 3-stage cp.async ring, ONE __syncthreads per iteration.
template<bool QKV>
__global__ void __launch_bounds__(256)
mma_gemm(const float* __restrict__ b0, const float* __restrict__ b1,
         const float* __restrict__ b2,
         const float* __restrict__ x1, const float* __restrict__ x2,
         float* __restrict__ outp) {
    extern __shared__ float dsm[];
    float* As = dsm;             // 3 stages x 4096
    float* Bs = dsm + 12288;     // 3 stages x 4096
    uint32_t a_base = smem_u32(As), b_base = smem_u32(Bs);

    int n0g = blockIdx.x * 128;
    int widx, n0;
    const float *A, *Wt, *bias;
    float* C = nullptr;
    if (QKV) {
        widx = n0g >> 9;
        n0 = n0g & 511;
        A = g_scratch + (widx == 0 ? OFF_XN : OFF_TN);
        Wt = g_wt + (size_t)widx * DD * DD + (size_t)n0 * DD;
        bias = (widx == 0) ? b0 : (widx == 1) ? b1 : b2;
        C = g_scratch + (widx == 0 ? OFF_Q : (widx == 1) ? OFF_K : OFF_V);
    } else {
        n0 = n0g;
        A = g_scratch + OFF_HS;
        Wt = g_wt + (size_t)3 * DD * DD + (size_t)n0 * DD;
        bias = b0;
    }

    int tid = threadIdx.x, lane = tid & 31, wid = tid >> 5;
    int wm = wid >> 2, wn = wid & 3;
    int gid = lane >> 2, tig = lane & 3;
    int m0 = blockIdx.y * 128;
    float c[4][4][4] = {};
    int r4 = tid >> 3, kc = (tid & 7) * 4;
    int sx = gid << 2;

    // prologue: stages 0, 1
    #pragma unroll
    for (int s = 0; s < 2; s++) {
        int so = s * 4096, k0 = s * 32;
        #pragma unroll
        for (int p = 0; p < 4; p++) {
            int row = r4 + p * 32;
            int kx = kc ^ ((row & 7) << 2);
            cp16(a_base + (uint32_t)(so + row*32 + kx)*4, A  + (size_t)(m0+row)*DD + k0 + kc);
            cp16(b_base + (uint32_t)(so + row*32 + kx)*4, Wt + (size_t)row*DD      + k0 + kc);
        }
        cp_commit();
    }

    for (int it = 0; it < 16; it++) {
        cp_wait1();           // group `it` complete (<=1 newer pending)
        __syncthreads();      // all warps done reading buffer (it+2)%3 from iter it-1

        if (it + 2 < 16) {
            int so = ((it + 2) % 3) * 4096;
            int k0 = (it + 2) * 32;
            #pragma unroll
            for (int p = 0; p < 4; p++) {
                int row = r4 + p * 32;
                int kx = kc ^ ((row & 7) << 2);
                cp16(a_base + (uint32_t)(so + row*32 + kx)*4, A  + (size_t)(m0+row)*DD + k0 + kc);
                cp16(b_base + (uint32_t)(so + row*32 + kx)*4, Wt + (size_t)row*DD      + k0 + kc);
            }
        }
        cp_commit();

        int st = (it % 3) * 4096;
        const uint32_t* Au = (const uint32_t*)(As + st);
        const uint32_t* Bu = (const uint32_t*)(Bs + st);
        #pragma unroll
        for (int ks = 0; ks < 4; ks++) {
            int kk = ks * 8;
            int c0 = (kk + tig) ^ sx;
            int c1 = (kk + tig + 4) ^ sx;
            uint32_t a[4][4];
            #pragma unroll
            for (int mi = 0; mi < 4; mi++) {
                int rm = (wm*64 + mi*16 + gid) * 32;
                a[mi][0] = Au[rm + c0];
                a[mi][1] = Au[rm + 8*32 + c0];
                a[mi][2] = Au[rm + c1];
                a[mi][3] = Au[rm + 8*32 + c1];
            }
            uint32_t b[4][2];
            #pragma unroll
            for (int ni = 0; ni < 4; ni++) {
                int rn = (wn*32 + ni*8 + gid) * 32;
                b[ni][0] = Bu[rn + c0];
                b[ni][1] = Bu[rn + c1];
            }
            #pragma unroll
            for (int mi = 0; mi < 4; mi++)
                #pragma unroll
                for (int ni = 0; ni < 4; ni++)
                    mma8(c[mi][ni], a[mi], b[ni]);
        }
    }

    #pragma unroll
    for (int mi = 0; mi < 4; mi++) {
        #pragma unroll
        for (int ni = 0; ni < 4; ni++) {
            #pragma unroll
            for (int r = 0; r < 4; r++) {
                int m = m0 + wm*64 + mi*16 + gid + ((r >= 2) ? 8 : 0);
                int n = n0 + wn*32 + ni*8 + 2*tig + (r & 1);
                float v = c[mi][ni][r] + bias[n];
                if (QKV) {
                    int b_ = m >> 9, nn = m & 511, h = n >> 6, d = n & 63;
                    C[(((size_t)(b_*H + h)*T + nn)*DH) + d] = rnd_tf32(v);
                } else {
                    const float* src = (m < NTOK/2) ? x1 + (size_t)m*DD
                                                    : x2 + (size_t)(m - NTOK/2)*DD;
                    outp[(size_t)m*DD + n] = v + src[n];
                }
            }
        }
    }
}

// ================= fused flash attention: scores + online softmax + P@V =================
// Block = 64 q-rows of one (b,h). 4 warps x 16 rows. BC=64 keys per iteration.
// smem (floats): sQ[4096] sK[4096] sV[4096] sP[4096] = 64KB  (mask read straight to regs)
__global__ void __launch_bounds__(128)
fa_kernel(const float* __restrict__ mask) {
    extern __shared__ float dsm[];
    float* sQ = dsm;
    float* sK = dsm + 4096;
    float* sV = dsm + 8192;
    float* sP = dsm + 12288;

    int bh = blockIdx.y, b = bh >> 3, h = bh & 7;
    int n0 = blockIdx.x * 64;
    const float* Q = g_scratch + OFF_Q + (size_t)bh*T*DH;
    const float* K = g_scratch + OFF_K + (size_t)bh*T*DH;
    const float* V = g_scratch + OFF_V + (size_t)bh*T*DH;

    int tid = threadIdx.x, lane = tid & 31, w = tid >> 5;
    int gid = lane >> 2, tig = lane & 3;
    int sx = gid << 2;
    int w16 = w * 16;
    int rA = w16 + gid, rB = rA + 8;     // local q-rows owned by this lane

    // rows of the mask this lane needs (fixed across kv tiles)
    const float* mrowA = mask + ((size_t)b*T + n0 + rA)*T;
    const float* mrowB = mask + ((size_t)b*T + n0 + rB)*T;

    // load Q tile (64 x 64), swizzle <<2
    int lr = tid >> 4;             // 0..7
    int lc4 = (tid & 15) * 4;      // 0..60
    #pragma unroll
    for (int p = 0; p < 8; p++) {
        int row = lr + p * 8;
        int cx = lc4 ^ ((row & 7) << 2);
        *(float4*)(sQ + row*64 + cx) = *(const float4*)(Q + (size_t)(n0+row)*DH + lc4);
    }

    float co[8][4] = {};
    float miA = -1e30f, miB = -1e30f;
    float lA = 0.0f, lB = 0.0f;

    for (int mt = 0; mt < T/64; mt++) {
        int m0 = mt * 64;
        __syncthreads();   // previous iteration's sK/sV fully consumed (orders sQ on mt=0)
        #pragma unroll
        for (int p = 0; p < 8; p++) {
            int row = lr + p * 8;
            int cx2 = lc4 ^ ((row & 7) << 2);
            int cx3 = lc4 ^ ((row & 7) << 3);
            *(float4*)(sK + row*64 + cx2) = *(const float4*)(K + (size_t)(m0+row)*DH + lc4);
            *(float4*)(sV + row*64 + cx3) = *(const float4*)(V + (size_t)(m0+row)*DH + lc4);
        }
        __syncthreads();

        // S = Q @ K^T  (warp: 16 rows x 64 cols)
        float cs[8][4] = {};
        const uint32_t* Qu = (const uint32_t*)sQ;
        const uint32_t* Ku = (const uint32_t*)sK;
        #pragma unroll
        for (int ks = 0; ks < 8; ks++) {
            int kk = ks * 8;
            int c0 = (kk + tig) ^ sx;
            int c1 = (kk + tig + 4) ^ sx;
            uint32_t a[4];
            int rm = (w16 + gid) * 64;
            a[0] = Qu[rm + c0];
            a[1] = Qu[rm + 8*64 + c0];
            a[2] = Qu[rm + c1];
            a[3] = Qu[rm + 8*64 + c1];
            #pragma unroll
            for (int ni = 0; ni < 8; ni++) {
                int rn = (ni*8 + gid) * 64;
                uint32_t bb[2];
                bb[0] = Ku[rn + c0];
                bb[1] = Ku[rn + c1];
                mma8(cs[ni], a, bb);
            }
        }

        // scale + mask (regs) + row max
        float rmA = -1e30f, rmB = -1e30f;
        #pragma unroll
        for (int ni = 0; ni < 8; ni++) {
            int col = ni*8 + 2*tig;
            float2 mA = *(const float2*)(mrowA + m0 + col);
            float2 mB = *(const float2*)(mrowB + m0 + col);
            cs[ni][0] = cs[ni][0]*0.125f + (1.0f - mA.x)*(-100000.0f);
            cs[ni][1] = cs[ni][1]*0.125f + (1.0f - mA.y)*(-100000.0f);
            cs[ni][2] = cs[ni][2]*0.125f + (1.0f - mB.x)*(-100000.0f);
            cs[ni][3] = cs[ni][3]*0.125f + (1.0f - mB.y)*(-100000.0f);
            rmA = fmaxf(rmA, fmaxf(cs[ni][0], cs[ni][1]));
            rmB = fmaxf(rmB, fmaxf(cs[ni][2], cs[ni][3]));
        }
        rmA = fmaxf(rmA, __shfl_xor_sync(0xffffffffu, rmA, 1));
        rmA = fmaxf(rmA, __shfl_xor_sync(0xffffffffu, rmA, 2));
        rmB = fmaxf(rmB, __shfl_xor_sync(0xffffffffu, rmB, 1));
        rmB = fmaxf(rmB, __shfl_xor_sync(0xffffffffu, rmB, 2));

        float mnA = fmaxf(miA, rmA), mnB = fmaxf(miB, rmB);
        float alA = __expf(miA - mnA), alB = __expf(miB - mnB);
        miA = mnA; miB = mnB;

        float sumA = 0.0f, sumB = 0.0f;
        #pragma unroll
        for (int ni = 0; ni < 8; ni++) {
            int col = ni*8 + 2*tig;
            float p0 = __expf(cs[ni][0] - mnA);
            float p1 = __expf(cs[ni][1] - mnA);
            float p2 = __expf(cs[ni][2] - mnB);
            float p3 = __expf(cs[ni][3] - mnB);
            sumA += p0 + p1; sumB += p2 + p3;
            float2 pa; pa.x = rnd_tf32(p0); pa.y = rnd_tf32(p1);
            float2 pb; pb.x = rnd_tf32(p2); pb.y = rnd_tf32(p3);
            *(float2*)(sP + rA*64 + (col ^ sx)) = pa;
            *(float2*)(sP + rB*64 + (col ^ sx)) = pb;
        }
        sumA += __shfl_xor_sync(0xffffffffu, sumA, 1);
        sumA += __shfl_xor_sync(0xffffffffu, sumA, 2);
        sumB += __shfl_xor_sync(0xffffffffu, sumB, 1);
        sumB += __shfl_xor_sync(0xffffffffu, sumB, 2);
        lA = lA * alA + sumA;
        lB = lB * alB + sumB;

        #pragma unroll
        for (int ni = 0; ni < 8; ni++) {
            co[ni][0] *= alA; co[ni][1] *= alA;
            co[ni][2] *= alB; co[ni][3] *= alB;
        }
        __syncwarp();   // sP rows are warp-private: warp-level fence suffices

        // O += P @ V
        const uint32_t* Pu = (const uint32_t*)sP;
        const uint32_t* Vu = (const uint32_t*)sV;
        #pragma unroll
        for (int ks = 0; ks < 8; ks++) {
            int kk = ks * 8;
            int c0 = (kk + tig) ^ sx;
            int c1 = (kk + tig + 4) ^ sx;
            uint32_t a[4];
            int rm = (w16 + gid) * 64;
            a[0] = Pu[rm + c0];
            a[1] = Pu[rm + 8*64 + c0];
            a[2] = Pu[rm + c1];
            a[3] = Pu[rm + 8*64 + c1];
            int klo = kk + tig, khi = kk + tig + 4;
            #pragma unroll
            for (int ni = 0; ni < 8; ni++) {
                int cn = ni*8 + gid;
                uint32_t bb[2];
                bb[0] = Vu[klo*64 + (cn ^ ((klo & 7) << 3))];
                bb[1] = Vu[khi*64 + (cn ^ ((khi & 7) << 3))];
                mma8(co[ni], a, bb);
            }
        }
    }

    // epilogue: normalize + write Y[b,n,D]
    float invA = 1.0f / lA, invB = 1.0f / lB;
    float* Y = g_scratch + OFF_Y;
    int nA = n0 + rA, nB = n0 + rB;
    #pragma unroll
    for (int ni = 0; ni < 8; ni++) {
        int dcol = h*DH + ni*8 + 2*tig;
        float2 oa; oa.x = co[ni][0]*invA; oa.y = co[ni][1]*invA;
        float2 ob; ob.x = co[ni][2]*invB; ob.y = co[ni][3]*invB;
        *(float2*)(Y + ((size_t)(b*T + nA))*DD + dcol) = oa;
        *(float2*)(Y + ((size_t)(b*T + nB))*DD + dcol) = ob;
    }
}

// ================= emb FiLM params (fp32) =================
__global__ void emb_kernel(const float* __restrict__ emb, const float* __restrict__ Wemb,
                           const float* __restrict__ bemb) {
    int b   = blockIdx.x >> 2;
    int col = (blockIdx.x & 3) * 256 + threadIdx.x;
    __shared__ float se[256];
    float acc = 0.0f;
    for (int kc = 0; kc < TE; kc += 256) {
        float e = emb[(size_t)b*TE + kc + threadIdx.x];
        se[threadIdx.x] = e / (1.0f + expf(-e));
        __syncthreads();
        #pragma unroll 8
        for (int kk = 0; kk < 256; kk++)
            acc += se[kk] * Wemb[(size_t)(kc + kk)*(2*DD) + col];
        __syncthreads();
    }
    g_scratch[OFF_SS + (size_t)b*(2*DD) + col] = acc + bemb[col];
}

// ================= hs = silu( LN(y)*(1+scale) + shift ), tf32-rounded =================
__global__ void film_kernel(const float* __restrict__ sbg, const float* __restrict__ sbb) {
    int r = blockIdx.x;
    int b = r >> 9;
    const float* y = g_scratch + OFF_Y + (size_t)r*DD;
    float* dst = g_scratch + OFF_HS + (size_t)r*DD;
    const float* ss = g_scratch + OFF_SS + (size_t)b*(2*DD);

    int tid = threadIdx.x;
    float4 v = ((const float4*)y)[tid];
    float s  = v.x + v.y + v.z + v.w;
    float sq = v.x*v.x + v.y*v.y + v.z*v.z + v.w*v.w;
    __shared__ float red[2][4];
    #pragma unroll
    for (int o = 16; o; o >>= 1) {
        s  += __shfl_xor_sync(0xffffffffu, s,  o);
        sq += __shfl_xor_sync(0xffffffffu, sq, o);
    }
    if ((tid & 31) == 0) { red[0][tid>>5] = s; red[1][tid>>5] = sq; }
    __syncthreads();
    s  = red[0][0] + red[0][1] + red[0][2] + red[0][3];
    sq = red[1][0] + red[1][1] + red[1][2] + red[1][3];
    float mean = s * (1.0f/DD);
    float var  = sq * (1.0f/DD) - mean*mean;
    float inv  = rsqrtf(var + 1e-5f);

    int col = tid * 4;
    float vv[4] = {v.x, v.y, v.z, v.w};
    float4 o;
    float* op = &o.x;
    #pragma unroll
    for (int cc = 0; cc < 4; cc++) {
        float ln = (vv[cc] - mean) * inv * sbg[col + cc] + sbb[col + cc];
        float hh = ln * (1.0f + ss[col + cc]) + ss[512 + col + cc];
        op[cc] = rnd_tf32(hh / (1.0f + expf(-hh)));
    }
    ((float4*)dst)[tid] = o;
}

// ================= launch =================
extern "C" void kernel_launch(void* const* d_in, const int* in_sizes, int n_in,
                              void* d_out, int out_size) {
    const float* x1    = (const float*)d_in[0];
    const float* x2    = (const float*)d_in[1];
    const float* emb   = (const float*)d_in[2];
    const float* mask  = (const float*)d_in[3];
    const float* ln_x_g = (const float*)d_in[4];
    const float* ln_x_b = (const float*)d_in[5];
    const float* ln_t_g = (const float*)d_in[6];
    const float* ln_t_b = (const float*)d_in[7];
    const float* Wq = (const float*)d_in[8];
    const float* bq = (const float*)d_in[9];
    const float* Wk = (const float*)d_in[10];
    const float* bk = (const float*)d_in[11];
    const float* Wv = (const float*)d_in[12];
    const float* bv = (const float*)d_in[13];
    const float* Wemb = (const float*)d_in[14];
    const float* bemb = (const float*)d_in[15];
    const float* sb_g = (const float*)d_in[16];
    const float* sb_b = (const float*)d_in[17];
    const float* Wout = (const float*)d_in[18];
    const float* bout = (const float*)d_in[19];
    float* out = (float*)d_out;

    cudaFuncSetAttribute(mma_gemm<true>,  cudaFuncAttributeMaxDynamicSharedMemorySize, 98304);
    cudaFuncSetAttribute(mma_gemm<false>, cudaFuncAttributeMaxDynamicSharedMemorySize, 98304);
    cudaFuncSetAttribute(fa_kernel,       cudaFuncAttributeMaxDynamicSharedMemorySize, 65536);

    wtrans4_kernel<<<dim3(16, 16, 4), dim3(32, 8)>>>(Wq, Wk, Wv, Wout);
    ln2_kernel<<<NTOK/2, 128>>>(x1, x2, ln_x_g, ln_x_b, ln_t_g, ln_t_b);

    // fused Q/K/V projection: N = 1536
    mma_gemm<true><<<dim3(12, NTOK/128), 256, 98304>>>(bq, bk, bv, x1, x2, nullptr);

    emb_kernel<<<B2*4, 256>>>(emb, Wemb, bemb);

    fa_kernel<<<dim3(T/64, B2*H), 128, 65536>>>(mask);

    film_kernel<<<NTOK, 128>>>(sb_g, sb_b);
    mma_gemm<false><<<dim3(4, NTOK/128), 256, 98304>>>(bout, nullptr, nullptr, x1, x2, out);
}

// round 7
// speedup vs baseline: 3.5670x; 1.1749x over previous
#include <cuda_runtime.h>
#include <math.h>
#include <stdint.h>

#define B2   32
#define T    512
#define DD   512
#define H    8
#define DH   64
#define TE   2048
#define NTOK (B2*T)               /* 16384 */
#define NELEM ((size_t)NTOK*DD)   /* 8388608 */

// ---------------- fp32 scratch ----------------
#define OFF_XN ((size_t)0)
#define OFF_TN (OFF_XN + NELEM)
#define OFF_Q  (OFF_TN + NELEM)   // head layout [b,h,n,dh]
#define OFF_K  (OFF_Q  + NELEM)
#define OFF_V  (OFF_K  + NELEM)
#define OFF_Y  (OFF_V  + NELEM)   // [b,n,D]
#define OFF_HS (OFF_Y  + NELEM)
#define OFF_SS (OFF_HS + NELEM)                     // [32][1024] FiLM params
#define OFF_EP (OFF_SS + (size_t)B2*2*DD)           // [16][32][1024] split-K partials
#define SCRATCH_TOTAL (OFF_EP + (size_t)16*B2*2*DD)

__device__ __align__(16) float g_scratch[SCRATCH_TOTAL];
__device__ __align__(16) float g_wt[4 * (size_t)DD * DD];   // transposed weights [n][k], tf32-rounded

// ---------------- helpers ----------------
__device__ __forceinline__ uint32_t f2tf32(float x) {
    uint32_t r;
    asm("cvt.rna.tf32.f32 %0, %1;" : "=r"(r) : "f"(x));
    return r;
}
__device__ __forceinline__ float rnd_tf32(float x) { return __uint_as_float(f2tf32(x)); }

__device__ __forceinline__ void mma8(float* c, const uint32_t* a, const uint32_t* b) {
    asm volatile(
        "mma.sync.aligned.m16n8k8.row.col.f32.tf32.tf32.f32 "
        "{%0,%1,%2,%3},{%4,%5,%6,%7},{%8,%9},{%0,%1,%2,%3};\n"
        : "+f"(c[0]), "+f"(c[1]), "+f"(c[2]), "+f"(c[3])
        : "r"(a[0]), "r"(a[1]), "r"(a[2]), "r"(a[3]), "r"(b[0]), "r"(b[1]));
}

__device__ __forceinline__ uint32_t smem_u32(const void* p) {
    uint32_t a;
    asm("{ .reg .u64 t; cvta.to.shared.u64 t, %1; cvt.u32.u64 %0, t; }" : "=r"(a) : "l"(p));
    return a;
}
__device__ __forceinline__ void cp16(uint32_t d, const void* s) {
    asm volatile("cp.async.cg.shared.global [%0], [%1], 16;\n" :: "r"(d), "l"(s));
}
__device__ __forceinline__ void cp_commit() {
    asm volatile("cp.async.commit_group;\n" ::: "memory");
}
__device__ __forceinline__ void cp_wait1() {
    asm volatile("cp.async.wait_group 1;\n" ::: "memory");
}

// ================= 4-in-1 weight transpose + tf32 round =================
__global__ void wtrans4_kernel(const float* __restrict__ W0, const float* __restrict__ W1,
                               const float* __restrict__ W2, const float* __restrict__ W3) {
    __shared__ float t[32][33];
    int wi = blockIdx.z;
    const float* W = (wi == 0) ? W0 : (wi == 1) ? W1 : (wi == 2) ? W2 : W3;
    float* Wt = g_wt + (size_t)wi * DD * DD;
    int nb = blockIdx.x * 32, kb = blockIdx.y * 32;
    int tx = threadIdx.x, ty = threadIdx.y;   // 32 x 8
    #pragma unroll
    for (int i = ty; i < 32; i += 8)
        t[i][tx] = W[(size_t)(kb + i) * DD + nb + tx];
    __syncthreads();
    #pragma unroll
    for (int i = ty; i < 32; i += 8)
        Wt[(size_t)(nb + i) * DD + kb + tx] = rnd_tf32(t[tx][i]);
}

// ================= fused LayerNorm: one block handles x1[r] & x2[r], writes 4 rows =================
__global__ void ln2_kernel(const float* __restrict__ x1, const float* __restrict__ x2,
                           const float* __restrict__ gx, const float* __restrict__ bx,
                           const float* __restrict__ gt, const float* __restrict__ bt) {
    int r = blockIdx.x;                // 0..NTOK/2-1
    int tid = threadIdx.x;             // 128 threads, 4 floats each
    float4 v1 = ((const float4*)(x1 + (size_t)r*DD))[tid];
    float4 v2 = ((const float4*)(x2 + (size_t)r*DD))[tid];

    float s1 = v1.x+v1.y+v1.z+v1.w, q1 = v1.x*v1.x+v1.y*v1.y+v1.z*v1.z+v1.w*v1.w;
    float s2 = v2.x+v2.y+v2.z+v2.w, q2 = v2.x*v2.x+v2.y*v2.y+v2.z*v2.z+v2.w*v2.w;

    __shared__ float red[4][4];
    #pragma unroll
    for (int o = 16; o; o >>= 1) {
        s1 += __shfl_xor_sync(0xffffffffu, s1, o);
        q1 += __shfl_xor_sync(0xffffffffu, q1, o);
        s2 += __shfl_xor_sync(0xffffffffu, s2, o);
        q2 += __shfl_xor_sync(0xffffffffu, q2, o);
    }
    if ((tid & 31) == 0) {
        int w = tid >> 5;
        red[0][w] = s1; red[1][w] = q1; red[2][w] = s2; red[3][w] = q2;
    }
    __syncthreads();
    s1 = red[0][0]+red[0][1]+red[0][2]+red[0][3];
    q1 = red[1][0]+red[1][1]+red[1][2]+red[1][3];
    s2 = red[2][0]+red[2][1]+red[2][2]+red[2][3];
    q2 = red[3][0]+red[3][1]+red[3][2]+red[3][3];
    float m1 = s1*(1.0f/DD), iv1 = rsqrtf(q1*(1.0f/DD) - m1*m1 + 1e-5f);
    float m2 = s2*(1.0f/DD), iv2 = rsqrtf(q2*(1.0f/DD) - m2*m2 + 1e-5f);

    float4 ggx = ((const float4*)gx)[tid], bbx = ((const float4*)bx)[tid];
    float4 ggt = ((const float4*)gt)[tid], bbt = ((const float4*)bt)[tid];

    float n1[4] = {(v1.x-m1)*iv1, (v1.y-m1)*iv1, (v1.z-m1)*iv1, (v1.w-m1)*iv1};
    float n2[4] = {(v2.x-m2)*iv2, (v2.y-m2)*iv2, (v2.z-m2)*iv2, (v2.w-m2)*iv2};
    const float* gxp = &ggx.x; const float* bxp = &bbx.x;
    const float* gtp = &ggt.x; const float* btp = &bbt.x;

    float4 o;
    float* op = &o.x;
    float* XN = g_scratch + OFF_XN;
    float* TN = g_scratch + OFF_TN;
    const int half = NTOK/2;

    #pragma unroll
    for (int c = 0; c < 4; c++) op[c] = rnd_tf32(n1[c]*gxp[c] + bxp[c]);
    ((float4*)(XN + (size_t)r*DD))[tid] = o;
    #pragma unroll
    for (int c = 0; c < 4; c++) op[c] = rnd_tf32(n2[c]*gxp[c] + bxp[c]);
    ((float4*)(XN + (size_t)(r+half)*DD))[tid] = o;
    #pragma unroll
    for (int c = 0; c < 4; c++) op[c] = rnd_tf32(n2[c]*gtp[c] + btp[c]);
    ((float4*)(TN + (size_t)r*DD))[tid] = o;
    #pragma unroll
    for (int c = 0; c < 4; c++) op[c] = rnd_tf32(n1[c]*gtp[c] + btp[c]);
    ((float4*)(TN + (size_t)(r+half)*DD))[tid] = o;
}

// ================= 3-stage pipelined tf32 MMA GEMM =================
// QKV=true : one launch for Q,K,V. n-global in [0,1536): widx = n>>9 selects weight/A/output.
// QKV=false: out-projection + bias + residual.
template<bool QKV>
__global__ void __launch_bounds__(256)
mma_gemm(const float* __restrict__ b0, const float* __restrict__ b1,
         const float* __restrict__ b2,
         const float* __restrict__ x1, const float* __restrict__ x2,
         float* __restrict__ outp) {
    extern __shared__ float dsm[];
    float* As = dsm;             // 3 stages x 4096
    float* Bs = dsm + 12288;     // 3 stages x 4096
    uint32_t a_base = smem_u32(As), b_base = smem_u32(Bs);

    int n0g = blockIdx.x * 128;
    int widx, n0;
    const float *A, *Wt, *bias;
    float* C = nullptr;
    if (QKV) {
        widx = n0g >> 9;
        n0 = n0g & 511;
        A = g_scratch + (widx == 0 ? OFF_XN : OFF_TN);
        Wt = g_wt + (size_t)widx * DD * DD + (size_t)n0 * DD;
        bias = (widx == 0) ? b0 : (widx == 1) ? b1 : b2;
        C = g_scratch + (widx == 0 ? OFF_Q : (widx == 1) ? OFF_K : OFF_V);
    } else {
        n0 = n0g;
        A = g_scratch + OFF_HS;
        Wt = g_wt + (size_t)3 * DD * DD + (size_t)n0 * DD;
        bias = b0;
    }

    int tid = threadIdx.x, lane = tid & 31, wid = tid >> 5;
    int wm = wid >> 2, wn = wid & 3;
    int gid = lane >> 2, tig = lane & 3;
    int m0 = blockIdx.y * 128;
    float c[4][4][4] = {};
    int r4 = tid >> 3, kc = (tid & 7) * 4;
    int sx = gid << 2;

    // prologue: stages 0, 1
    #pragma unroll
    for (int s = 0; s < 2; s++) {
        int so = s * 4096, k0 = s * 32;
        #pragma unroll
        for (int p = 0; p < 4; p++) {
            int row = r4 + p * 32;
            int kx = kc ^ ((row & 7) << 2);
            cp16(a_base + (uint32_t)(so + row*32 + kx)*4, A  + (size_t)(m0+row)*DD + k0 + kc);
            cp16(b_base + (uint32_t)(so + row*32 + kx)*4, Wt + (size_t)row*DD      + k0 + kc);
        }
        cp_commit();
    }

    for (int it = 0; it < 16; it++) {
        cp_wait1();
        __syncthreads();

        if (it + 2 < 16) {
            int so = ((it + 2) % 3) * 4096;
            int k0 = (it + 2) * 32;
            #pragma unroll
            for (int p = 0; p < 4; p++) {
                int row = r4 + p * 32;
                int kx = kc ^ ((row & 7) << 2);
                cp16(a_base + (uint32_t)(so + row*32 + kx)*4, A  + (size_t)(m0+row)*DD + k0 + kc);
                cp16(b_base + (uint32_t)(so + row*32 + kx)*4, Wt + (size_t)row*DD      + k0 + kc);
            }
        }
        cp_commit();

        int st = (it % 3) * 4096;
        const uint32_t* Au = (const uint32_t*)(As + st);
        const uint32_t* Bu = (const uint32_t*)(Bs + st);
        #pragma unroll
        for (int ks = 0; ks < 4; ks++) {
            int kk = ks * 8;
            int c0 = (kk + tig) ^ sx;
            int c1 = (kk + tig + 4) ^ sx;
            uint32_t a[4][4];
            #pragma unroll
            for (int mi = 0; mi < 4; mi++) {
                int rm = (wm*64 + mi*16 + gid) * 32;
                a[mi][0] = Au[rm + c0];
                a[mi][1] = Au[rm + 8*32 + c0];
                a[mi][2] = Au[rm + c1];
                a[mi][3] = Au[rm + 8*32 + c1];
            }
            uint32_t b[4][2];
            #pragma unroll
            for (int ni = 0; ni < 4; ni++) {
                int rn = (wn*32 + ni*8 + gid) * 32;
                b[ni][0] = Bu[rn + c0];
                b[ni][1] = Bu[rn + c1];
            }
            #pragma unroll
            for (int mi = 0; mi < 4; mi++)
                #pragma unroll
                for (int ni = 0; ni < 4; ni++)
                    mma8(c[mi][ni], a[mi], b[ni]);
        }
    }

    #pragma unroll
    for (int mi = 0; mi < 4; mi++) {
        #pragma unroll
        for (int ni = 0; ni < 4; ni++) {
            #pragma unroll
            for (int r = 0; r < 4; r++) {
                int m = m0 + wm*64 + mi*16 + gid + ((r >= 2) ? 8 : 0);
                int n = n0 + wn*32 + ni*8 + 2*tig + (r & 1);
                float v = c[mi][ni][r] + bias[n];
                if (QKV) {
                    int b_ = m >> 9, nn = m & 511, h = n >> 6, d = n & 63;
                    C[(((size_t)(b_*H + h)*T + nn)*DH) + d] = rnd_tf32(v);
                } else {
                    const float* src = (m < NTOK/2) ? x1 + (size_t)m*DD
                                                    : x2 + (size_t)(m - NTOK/2)*DD;
                    outp[(size_t)m*DD + n] = v + src[n];
                }
            }
        }
    }
}

// ================= fused flash attention: scores + online softmax + P@V =================
__global__ void __launch_bounds__(128)
fa_kernel(const float* __restrict__ mask) {
    extern __shared__ float dsm[];
    float* sQ = dsm;
    float* sK = dsm + 4096;
    float* sV = dsm + 8192;
    float* sP = dsm + 12288;

    int bh = blockIdx.y, b = bh >> 3, h = bh & 7;
    int n0 = blockIdx.x * 64;
    const float* Q = g_scratch + OFF_Q + (size_t)bh*T*DH;
    const float* K = g_scratch + OFF_K + (size_t)bh*T*DH;
    const float* V = g_scratch + OFF_V + (size_t)bh*T*DH;

    int tid = threadIdx.x, lane = tid & 31, w = tid >> 5;
    int gid = lane >> 2, tig = lane & 3;
    int sx = gid << 2;
    int w16 = w * 16;
    int rA = w16 + gid, rB = rA + 8;

    const float* mrowA = mask + ((size_t)b*T + n0 + rA)*T;
    const float* mrowB = mask + ((size_t)b*T + n0 + rB)*T;

    int lr = tid >> 4;
    int lc4 = (tid & 15) * 4;
    #pragma unroll
    for (int p = 0; p < 8; p++) {
        int row = lr + p * 8;
        int cx = lc4 ^ ((row & 7) << 2);
        *(float4*)(sQ + row*64 + cx) = *(const float4*)(Q + (size_t)(n0+row)*DH + lc4);
    }

    float co[8][4] = {};
    float miA = -1e30f, miB = -1e30f;
    float lA = 0.0f, lB = 0.0f;

    for (int mt = 0; mt < T/64; mt++) {
        int m0 = mt * 64;
        __syncthreads();
        #pragma unroll
        for (int p = 0; p < 8; p++) {
            int row = lr + p * 8;
            int cx2 = lc4 ^ ((row & 7) << 2);
            int cx3 = lc4 ^ ((row & 7) << 3);
            *(float4*)(sK + row*64 + cx2) = *(const float4*)(K + (size_t)(m0+row)*DH + lc4);
            *(float4*)(sV + row*64 + cx3) = *(const float4*)(V + (size_t)(m0+row)*DH + lc4);
        }
        __syncthreads();

        float cs[8][4] = {};
        const uint32_t* Qu = (const uint32_t*)sQ;
        const uint32_t* Ku = (const uint32_t*)sK;
        #pragma unroll
        for (int ks = 0; ks < 8; ks++) {
            int kk = ks * 8;
            int c0 = (kk + tig) ^ sx;
            int c1 = (kk + tig + 4) ^ sx;
            uint32_t a[4];
            int rm = (w16 + gid) * 64;
            a[0] = Qu[rm + c0];
            a[1] = Qu[rm + 8*64 + c0];
            a[2] = Qu[rm + c1];
            a[3] = Qu[rm + 8*64 + c1];
            #pragma unroll
            for (int ni = 0; ni < 8; ni++) {
                int rn = (ni*8 + gid) * 64;
                uint32_t bb[2];
                bb[0] = Ku[rn + c0];
                bb[1] = Ku[rn + c1];
                mma8(cs[ni], a, bb);
            }
        }

        float rmA = -1e30f, rmB = -1e30f;
        #pragma unroll
        for (int ni = 0; ni < 8; ni++) {
            int col = ni*8 + 2*tig;
            float2 mA = *(const float2*)(mrowA + m0 + col);
            float2 mB = *(const float2*)(mrowB + m0 + col);
            cs[ni][0] = cs[ni][0]*0.125f + (1.0f - mA.x)*(-100000.0f);
            cs[ni][1] = cs[ni][1]*0.125f + (1.0f - mA.y)*(-100000.0f);
            cs[ni][2] = cs[ni][2]*0.125f + (1.0f - mB.x)*(-100000.0f);
            cs[ni][3] = cs[ni][3]*0.125f + (1.0f - mB.y)*(-100000.0f);
            rmA = fmaxf(rmA, fmaxf(cs[ni][0], cs[ni][1]));
            rmB = fmaxf(rmB, fmaxf(cs[ni][2], cs[ni][3]));
        }
        rmA = fmaxf(rmA, __shfl_xor_sync(0xffffffffu, rmA, 1));
        rmA = fmaxf(rmA, __shfl_xor_sync(0xffffffffu, rmA, 2));
        rmB = fmaxf(rmB, __shfl_xor_sync(0xffffffffu, rmB, 1));
        rmB = fmaxf(rmB, __shfl_xor_sync(0xffffffffu, rmB, 2));

        float mnA = fmaxf(miA, rmA), mnB = fmaxf(miB, rmB);
        float alA = __expf(miA - mnA), alB = __expf(miB - mnB);
        miA = mnA; miB = mnB;

        float sumA = 0.0f, sumB = 0.0f;
        #pragma unroll
        for (int ni = 0; ni < 8; ni++) {
            int col = ni*8 + 2*tig;
            float p0 = __expf(cs[ni][0] - mnA);
            float p1 = __expf(cs[ni][1] - mnA);
            float p2 = __expf(cs[ni][2] - mnB);
            float p3 = __expf(cs[ni][3] - mnB);
            sumA += p0 + p1; sumB += p2 + p3;
            float2 pa; pa.x = rnd_tf32(p0); pa.y = rnd_tf32(p1);
            float2 pb; pb.x = rnd_tf32(p2); pb.y = rnd_tf32(p3);
            *(float2*)(sP + rA*64 + (col ^ sx)) = pa;
            *(float2*)(sP + rB*64 + (col ^ sx)) = pb;
        }
        sumA += __shfl_xor_sync(0xffffffffu, sumA, 1);
        sumA += __shfl_xor_sync(0xffffffffu, sumA, 2);
        sumB += __shfl_xor_sync(0xffffffffu, sumB, 1);
        sumB += __shfl_xor_sync(0xffffffffu, sumB, 2);
        lA = lA * alA + sumA;
        lB = lB * alB + sumB;

        #pragma unroll
        for (int ni = 0; ni < 8; ni++) {
            co[ni][0] *= alA; co[ni][1] *= alA;
            co[ni][2] *= alB; co[ni][3] *= alB;
        }
        __syncwarp();

        const uint32_t* Pu = (const uint32_t*)sP;
        const uint32_t* Vu = (const uint32_t*)sV;
        #pragma unroll
        for (int ks = 0; ks < 8; ks++) {
            int kk = ks * 8;
            int c0 = (kk + tig) ^ sx;
            int c1 = (kk + tig + 4) ^ sx;
            uint32_t a[4];
            int rm = (w16 + gid) * 64;
            a[0] = Pu[rm + c0];
            a[1] = Pu[rm + 8*64 + c0];
            a[2] = Pu[rm + c1];
            a[3] = Pu[rm + 8*64 + c1];
            int klo = kk + tig, khi = kk + tig + 4;
            #pragma unroll
            for (int ni = 0; ni < 8; ni++) {
                int cn = ni*8 + gid;
                uint32_t bb[2];
                bb[0] = Vu[klo*64 + (cn ^ ((klo & 7) << 3))];
                bb[1] = Vu[khi*64 + (cn ^ ((khi & 7) << 3))];
                mma8(co[ni], a, bb);
            }
        }
    }

    float invA = 1.0f / lA, invB = 1.0f / lB;
    float* Y = g_scratch + OFF_Y;
    int nA = n0 + rA, nB = n0 + rB;
    #pragma unroll
    for (int ni = 0; ni < 8; ni++) {
        int dcol = h*DH + ni*8 + 2*tig;
        float2 oa; oa.x = co[ni][0]*invA; oa.y = co[ni][1]*invA;
        float2 ob; ob.x = co[ni][2]*invB; ob.y = co[ni][3]*invB;
        *(float2*)(Y + ((size_t)(b*T + nA))*DD + dcol) = oa;
        *(float2*)(Y + ((size_t)(b*T + nB))*DD + dcol) = ob;
    }
}

// ================= emb FiLM GEMM, split-K phase 1 =================
// grid (16 colchunks x 16 ksplits), 256 threads.
// Each block: silu(emb[all 32 b][k0:k0+128]) in smem, thread = (col, 8-batch group).
__global__ void __launch_bounds__(256)
emb2_kernel(const float* __restrict__ emb, const float* __restrict__ Wemb) {
    __shared__ float se[32 * 129];
    int col0 = blockIdx.x * 64, k0 = blockIdx.y * 128;
    int tid = threadIdx.x;
    for (int i = tid; i < 32 * 128; i += 256) {
        int b = i >> 7, kk = i & 127;
        float e = emb[(size_t)b * TE + k0 + kk];
        se[b * 129 + kk] = e / (1.0f + __expf(-e));
    }
    __syncthreads();

    int col = col0 + (tid & 63);
    int bg = (tid >> 6) << 3;          // 0,8,16,24
    float acc[8] = {};
    #pragma unroll 4
    for (int kk = 0; kk < 128; kk++) {
        float wv = Wemb[(size_t)(k0 + kk) * (2 * DD) + col];
        #pragma unroll
        for (int j = 0; j < 8; j++)
            acc[j] += se[(bg + j) * 129 + kk] * wv;
    }
    float* P = g_scratch + OFF_EP + (size_t)blockIdx.y * (B2 * 2 * DD);
    #pragma unroll
    for (int j = 0; j < 8; j++)
        P[(size_t)(bg + j) * (2 * DD) + col] = acc[j];
}

// ================= emb split-K phase 2: reduce 16 partials + bias =================
__global__ void embred_kernel(const float* __restrict__ bemb) {
    int i = blockIdx.x * 256 + threadIdx.x;   // 0 .. 32*1024-1
    float s = bemb[i & (2 * DD - 1)];
    #pragma unroll
    for (int ks = 0; ks < 16; ks++)
        s += g_scratch[OFF_EP + (size_t)ks * (B2 * 2 * DD) + i];
    g_scratch[OFF_SS + i] = s;
}

// ================= hs = silu( LN(y)*(1+scale) + shift ), tf32-rounded =================
__global__ void film_kernel(const float* __restrict__ sbg, const float* __restrict__ sbb) {
    int r = blockIdx.x;
    int b = r >> 9;
    const float* y = g_scratch + OFF_Y + (size_t)r*DD;
    float* dst = g_scratch + OFF_HS + (size_t)r*DD;
    const float* ss = g_scratch + OFF_SS + (size_t)b*(2*DD);

    int tid = threadIdx.x;
    float4 v = ((const float4*)y)[tid];
    float s  = v.x + v.y + v.z + v.w;
    float sq = v.x*v.x + v.y*v.y + v.z*v.z + v.w*v.w;
    __shared__ float red[2][4];
    #pragma unroll
    for (int o = 16; o; o >>= 1) {
        s  += __shfl_xor_sync(0xffffffffu, s,  o);
        sq += __shfl_xor_sync(0xffffffffu, sq, o);
    }
    if ((tid & 31) == 0) { red[0][tid>>5] = s; red[1][tid>>5] = sq; }
    __syncthreads();
    s  = red[0][0] + red[0][1] + red[0][2] + red[0][3];
    sq = red[1][0] + red[1][1] + red[1][2] + red[1][3];
    float mean = s * (1.0f/DD);
    float var  = sq * (1.0f/DD) - mean*mean;
    float inv  = rsqrtf(var + 1e-5f);

    int col = tid * 4;
    float vv[4] = {v.x, v.y, v.z, v.w};
    float4 o;
    float* op = &o.x;
    #pragma unroll
    for (int cc = 0; cc < 4; cc++) {
        float ln = (vv[cc] - mean) * inv * sbg[col + cc] + sbb[col + cc];
        float hh = ln * (1.0f + ss[col + cc]) + ss[512 + col + cc];
        op[cc] = rnd_tf32(hh / (1.0f + expf(-hh)));
    }
    ((float4*)dst)[tid] = o;
}

// ================= launch =================
extern "C" void kernel_launch(void* const* d_in, const int* in_sizes, int n_in,
                              void* d_out, int out_size) {
    const float* x1    = (const float*)d_in[0];
    const float* x2    = (const float*)d_in[1];
    const float* emb   = (const float*)d_in[2];
    const float* mask  = (const float*)d_in[3];
    const float* ln_x_g = (const float*)d_in[4];
    const float* ln_x_b = (const float*)d_in[5];
    const float* ln_t_g = (const float*)d_in[6];
    const float* ln_t_b = (const float*)d_in[7];
    const float* Wq = (const float*)d_in[8];
    const float* bq = (const float*)d_in[9];
    const float* Wk = (const float*)d_in[10];
    const float* bk = (const float*)d_in[11];
    const float* Wv = (const float*)d_in[12];
    const float* bv = (const float*)d_in[13];
    const float* Wemb = (const float*)d_in[14];
    const float* bemb = (const float*)d_in[15];
    const float* sb_g = (const float*)d_in[16];
    const float* sb_b = (const float*)d_in[17];
    const float* Wout = (const float*)d_in[18];
    const float* bout = (const float*)d_in[19];
    float* out = (float*)d_out;

    cudaFuncSetAttribute(mma_gemm<true>,  cudaFuncAttributeMaxDynamicSharedMemorySize, 98304);
    cudaFuncSetAttribute(mma_gemm<false>, cudaFuncAttributeMaxDynamicSharedMemorySize, 98304);
    cudaFuncSetAttribute(fa_kernel,       cudaFuncAttributeMaxDynamicSharedMemorySize, 65536);

    wtrans4_kernel<<<dim3(16, 16, 4), dim3(32, 8)>>>(Wq, Wk, Wv, Wout);
    ln2_kernel<<<NTOK/2, 128>>>(x1, x2, ln_x_g, ln_x_b, ln_t_g, ln_t_b);

    // fused Q/K/V projection: N = 1536
    mma_gemm<true><<<dim3(12, NTOK/128), 256, 98304>>>(bq, bk, bv, x1, x2, nullptr);

    // FiLM emb GEMM (split-K, two phases)
    emb2_kernel<<<dim3(16, 16), 256>>>(emb, Wemb);
    embred_kernel<<<(B2*2*DD)/256, 256>>>(bemb);

    fa_kernel<<<dim3(T/64, B2*H), 128, 65536>>>(mask);

    film_kernel<<<NTOK, 128>>>(sb_g, sb_b);
    mma_gemm<false><<<dim3(4, NTOK/128), 256, 98304>>>(bout, nullptr, nullptr, x1, x2, out);
}